// round 11
// baseline (speedup 1.0000x reference)
#include <cuda_runtime.h>
#include <math.h>

// SpritesAndTexturesCoordinateDecoder — bf16 split mma.sync decoder, v6.
// A-fragments in thread-private SMEM slabs (plain C++ accesses so the compiler
// tracks dependencies — v5's inline-asm LDS got reordered across the STS).
// Register state fits 128 regs -> 4 warps/SMSP (16 warps/SM).

typedef unsigned int u32;

__device__ __align__(16) uint4 g_Bfrag[5][4096];   // [layer][(ks*16+nt)*32+lane] {hiB0,hiB1,loB0,loB1}
__device__ float g_b0[8 * 128], g_bt0[8 * 128];
__device__ float g_swsh[128], g_swt2[384];

__device__ __forceinline__ float lrelu_s2(float v) {
    return fmaf(0.84852813742385703f, v, 0.56568542494923801f * fabsf(v));
}
__device__ __forceinline__ void my_sincos(float x, float* sp, float* cp) {
    float k = rintf(x * 0.63661977236758134f);
    int   q = (int)k;
    float r = fmaf(k, -1.5707963705062866f, x);
    r       = fmaf(k,  4.3711390001862456e-8f, r);
    float r2 = r * r;
    float p  = fmaf(r2, fmaf(r2, -1.9841271e-4f, 8.3333310e-3f), -1.6666667e-1f);
    float s  = fmaf(p * r2, r, r);
    float qq = fmaf(r2, fmaf(r2, 2.4801587e-5f, -1.3888889e-3f), 4.1666668e-2f);
    float c  = fmaf(qq * r2, r2, fmaf(r2, -0.5f, 1.f));
    int   qm = q & 3;
    float sv = (qm & 1) ? c : s;
    float cv = (qm & 1) ? s : c;
    if (qm == 1 || qm == 2) cv = -cv;
    if (qm == 2 || qm == 3) sv = -sv;
    *sp = sv; *cp = cv;
}
__device__ __forceinline__ u32 bfbits32(float v) {
    u32 r; asm("{ .reg .b16 h; cvt.rn.bf16.f32 h, %1; mov.b32 %0, {h, 0}; }" : "=r"(r) : "f"(v));
    return r & 0xFFFFu;
}
__device__ __forceinline__ void mma4(float* c, const u32* a, u32 b0, u32 b1) {
    asm("mma.sync.aligned.m16n8k16.row.col.f32.bf16.bf16.f32 "
        "{%0,%1,%2,%3}, {%4,%5,%6,%7}, {%8,%9}, {%0,%1,%2,%3};"
        : "+f"(c[0]), "+f"(c[1]), "+f"(c[2]), "+f"(c[3])
        : "r"(a[0]), "r"(a[1]), "r"(a[2]), "r"(a[3]), "r"(b0), "r"(b1));
}
__device__ __forceinline__ void split2(float v0, float v1, u32& hi, u32& lo) {
    u32 u0 = __float_as_uint(v0), u1 = __float_as_uint(v1);
    hi = __byte_perm(u0, u1, 0x7632);
    float l0 = v0 - __uint_as_float(u0 & 0xFFFF0000u);
    float l1 = v1 - __uint_as_float(u1 & 0xFFFF0000u);
    asm("cvt.rn.bf16x2.f32 %0, %1, %2;" : "=r"(lo) : "f"(l1), "f"(l0));
}

// Per-warp slab: u32[2048] = 8KB. hi: [ks*128 + lane*4 + reg], lo: +1024.
// All accesses thread-private -> no sync, compiler-ordered.

// MODE: 0 normal, 1 = L2 (shape partials), 2 = last (texture partials, no split)
template <int NKS, int MODE>
__device__ __forceinline__ void run_layer(const uint4* __restrict__ wfrag,
                                          const float* __restrict__ bias,
                                          u32* ap, int lane, int q, float* hp)
{
    float acc[16][4];
#pragma unroll
    for (int nt = 0; nt < 16; nt++)
        acc[nt][0] = acc[nt][1] = acc[nt][2] = acc[nt][3] = 0.f;

    const uint4* wp = wfrag + lane;
#pragma unroll
    for (int ks = 0; ks < NKS; ks++) {
        uint4 ahv = *(const uint4*)(ap + ks * 128);
        uint4 alv = *(const uint4*)(ap + 1024 + ks * 128);
        u32 ahc[4] = { ahv.x, ahv.y, ahv.z, ahv.w };
        u32 alc[4] = { alv.x, alv.y, alv.z, alv.w };
#pragma unroll
        for (int g = 0; g < 4; g++) {
            int nt = g * 4;
            const uint4* p = wp + (ks * 16 + nt) * 32;
            uint4 fa = __ldg(p);
            uint4 fb = __ldg(p + 32);
            uint4 fc = __ldg(p + 64);
            uint4 fd = __ldg(p + 96);
            mma4(acc[nt],     ahc, fa.x, fa.y);
            mma4(acc[nt + 1], ahc, fb.x, fb.y);
            mma4(acc[nt + 2], ahc, fc.x, fc.y);
            mma4(acc[nt + 3], ahc, fd.x, fd.y);
            mma4(acc[nt],     ahc, fa.z, fa.w);
            mma4(acc[nt + 1], ahc, fb.z, fb.w);
            mma4(acc[nt + 2], ahc, fc.z, fc.w);
            mma4(acc[nt + 3], ahc, fd.z, fd.w);
            mma4(acc[nt],     alc, fa.x, fa.y);
            mma4(acc[nt + 1], alc, fb.x, fb.y);
            mma4(acc[nt + 2], alc, fc.x, fc.y);
            mma4(acc[nt + 3], alc, fd.x, fd.y);
        }
    }
#pragma unroll
    for (int nt = 0; nt < 16; nt++) {
        float2 b = __ldg((const float2*)(bias + nt * 8 + 2 * q));
        float v0 = lrelu_s2(acc[nt][0] + b.x), v1 = lrelu_s2(acc[nt][1] + b.y);
        float v2 = lrelu_s2(acc[nt][2] + b.x), v3 = lrelu_s2(acc[nt][3] + b.y);
        int ch = nt * 8 + 2 * q;
        if (MODE == 1) {
            float2 wv = __ldg((const float2*)(g_swsh + ch));
            hp[0] = fmaf(v0, wv.x, fmaf(v1, wv.y, hp[0]));
            hp[1] = fmaf(v2, wv.x, fmaf(v3, wv.y, hp[1]));
        }
        if (MODE == 2) {
#pragma unroll
            for (int c = 0; c < 3; c++) {
                float2 wv = __ldg((const float2*)(g_swt2 + c * 128 + ch));
                hp[2 * c]     = fmaf(v0, wv.x, fmaf(v1, wv.y, hp[2 * c]));
                hp[2 * c + 1] = fmaf(v2, wv.x, fmaf(v3, wv.y, hp[2 * c + 1]));
            }
        } else {
            // next-layer A regs (2hf, 2hf+1) of k-step ks2 = nt>>1
            int ks2 = nt >> 1, hf = nt & 1;
            u32 h0, l0, h1, l1;
            split2(v0, v1, h0, l0);
            split2(v2, v3, h1, l1);
            *(uint2*)(ap + ks2 * 128 + hf * 2)        = make_uint2(h0, h1);
            *(uint2*)(ap + 1024 + ks2 * 128 + hf * 2) = make_uint2(l0, l1);
        }
    }
}

__global__ void prep_kernel(
    const float* __restrict__ ws0, const float* __restrict__ bs0, const float* __restrict__ sc,
    const float* __restrict__ ws1, const float* __restrict__ ws2, const float* __restrict__ wsh,
    const float* __restrict__ wt0, const float* __restrict__ bt0, const float* __restrict__ tc,
    const float* __restrict__ wt1, const float* __restrict__ wt2, int B)
{
    const float s0 = 1.f / sqrtf(96.f), s1 = 1.f / sqrtf(128.f), st0 = 1.f / sqrtf(192.f);
    int nth = blockDim.x * gridDim.x;
    int tid0 = blockIdx.x * blockDim.x + threadIdx.x;

    for (int l = 0; l < 5; l++) {
        int KS; const float* src; float scl; int srcw;
        if      (l == 0) { KS = 2; src = ws0; scl = s0;  srcw = 96;  }
        else if (l == 1) { KS = 8; src = ws1; scl = s1;  srcw = 128; }
        else if (l == 2) { KS = 8; src = ws2; scl = s1;  srcw = 128; }
        else if (l == 3) { KS = 8; src = wt0; scl = st0; srcw = 192; }
        else             { KS = 8; src = wt1; scl = s1;  srcw = 128; }
        int tot = KS * 512;
        for (int idx = tid0; idx < tot; idx += nth) {
            int ks = idx >> 9, rem = idx & 511, nt = rem >> 5, lane = rem & 31;
            int q = lane & 3, gg = lane >> 2;
            int n = nt * 8 + gg;
            int ka = ks * 16 + 2 * q;
            float w[4];
            w[0] = src[n * srcw + ka] * scl;
            w[1] = src[n * srcw + ka + 1] * scl;
            w[2] = src[n * srcw + ka + 8] * scl;
            w[3] = src[n * srcw + ka + 9] * scl;
            u32 h[4], lo[4];
            for (int i = 0; i < 4; i++) {
                u32 ub = __float_as_uint(w[i]) & 0xFFFF0000u;
                h[i] = ub >> 16;
                lo[i] = bfbits32(w[i] - __uint_as_float(ub));
            }
            uint4 f;
            f.x = h[0] | (h[1] << 16);
            f.y = h[2] | (h[3] << 16);
            f.z = lo[0] | (lo[1] << 16);
            f.w = lo[2] | (lo[3] << 16);
            g_Bfrag[l][(ks * 16 + nt) * 32 + lane] = f;
        }
    }
    for (int i = tid0; i < 128; i += nth) g_swsh[i] = wsh[i] * s1;
    for (int i = tid0; i < 384; i += nth) g_swt2[i] = wt2[i] * s1;
    for (int idx = tid0; idx < B * 128 && idx < 8 * 128; idx += nth) {
        int b = idx >> 7, j = idx & 127;
        float a = 0.f, t = 0.f;
        for (int m = 0; m < 64; m++) {
            a += sc[b * 64 + m] * ws0[j * 96 + 32 + m];
            t += tc[b * 64 + m] * wt0[j * 192 + 128 + m];
        }
        g_b0 [b * 128 + j] = bs0[j] + a * s0;
        g_bt0[b * 128 + j] = bt0[j] + t * st0;
    }
}

__global__ __launch_bounds__(128, 4)
void decoder_kernel(const float* __restrict__ coords,
                    const float* __restrict__ bs1, const float* __restrict__ bs2,
                    const float* __restrict__ bsh, const float* __restrict__ bt1,
                    const float* __restrict__ bt2,
                    float* __restrict__ out, int HW, int BHW)
{
    __shared__ __align__(16) u32 sAmem[4][2048];   // 4 warps x 8KB

    int tid = threadIdx.x;
    int lane = tid & 31, w = tid >> 5;
    int q = lane & 3, g = lane >> 2;
    int base = blockIdx.x * 64;          // 4 warps x 16 px
    int batch = base / HW;
    int px0 = base + w * 16 + g, px1 = px0 + 8;
    u32* ap = &sAmem[w][lane * 4];

    float2 crd0 = __ldg(&((const float2*)coords)[px0]);
    float2 crd1 = __ldg(&((const float2*)coords)[px1]);

    // ---- embedding -> A fragments for L0 (K=32 => ksteps 0,1), straight to smem
#pragma unroll
    for (int ks = 0; ks < 2; ks++) {
#pragma unroll
        for (int h = 0; h < 2; h++) {
            int s = 4 * ks + 2 * h + (q >> 1);
            float scl = 0.1f * (float)(1 << s);
#pragma unroll
            for (int row = 0; row < 2; row++) {
                float cx = (row ? crd1.x : crd0.x) * scl;
                float cy = (row ? crd1.y : crd0.y) * scl;
                float sx, cxv, sy, cyv;
                my_sincos(cx, &sx, &cxv);
                my_sincos(cy, &sy, &cyv);
                float v0 = (q & 1) ? cxv : sx;
                float v1 = (q & 1) ? cyv : sy;
                u32 hi, lo;
                split2(v0, v1, hi, lo);
                ap[ks * 128 + 2 * h + row]        = hi;
                ap[1024 + ks * 128 + 2 * h + row] = lo;
            }
        }
    }

    float dummy[1];
    run_layer<2, 0>(g_Bfrag[0], g_b0 + batch * 128, ap, lane, q, dummy);   // L0
    run_layer<8, 0>(g_Bfrag[1], bs1,                ap, lane, q, dummy);   // L1

    // L2 + shape head partials
    float pS[2] = {0.f, 0.f};
    run_layer<8, 1>(g_Bfrag[2], bs2, ap, lane, q, pS);
    {
        pS[0] += __shfl_xor_sync(0xffffffffu, pS[0], 1);
        pS[0] += __shfl_xor_sync(0xffffffffu, pS[0], 2);
        pS[1] += __shfl_xor_sync(0xffffffffu, pS[1], 1);
        pS[1] += __shfl_xor_sync(0xffffffffu, pS[1], 2);
        if (q == 0) {
            float bv = __ldg(bsh);
            float r0 = sqrtf(crd0.x * crd0.x + crd0.y * crd0.y);
            float r1 = sqrtf(crd1.x * crd1.x + crd1.y * crd1.y);
            out[px0] = (pS[0] + bv) * (1.f - tanhf(fmaxf(r0 - 1.f, 0.f)));
            out[px1] = (pS[1] + bv) * (1.f - tanhf(fmaxf(r1 - 1.f, 0.f)));
        }
    }

    run_layer<8, 0>(g_Bfrag[3], g_bt0 + batch * 128, ap, lane, q, dummy);  // T0

    // T1 + texture head partials
    float pT[6] = {0.f, 0.f, 0.f, 0.f, 0.f, 0.f};
    run_layer<8, 2>(g_Bfrag[4], bt1, ap, lane, q, pT);
    {
#pragma unroll
        for (int i = 0; i < 6; i++) {
            pT[i] += __shfl_xor_sync(0xffffffffu, pT[i], 1);
            pT[i] += __shfl_xor_sync(0xffffffffu, pT[i], 2);
        }
        if (q == 0) {
            float* tp = out + BHW;
#pragma unroll
            for (int c = 0; c < 3; c++) {
                float bv = __ldg(bt2 + c);
                tp[3 * px0 + c] = pT[2 * c] + bv;
                tp[3 * px1 + c] = pT[2 * c + 1] + bv;
            }
        }
    }
}

extern "C" void kernel_launch(void* const* d_in, const int* in_sizes, int n_in,
                              void* d_out, int out_size)
{
    const float* coords = (const float*)d_in[0];
    const float* sc  = (const float*)d_in[1];
    const float* tc  = (const float*)d_in[2];
    const float* ws0 = (const float*)d_in[3];  const float* bs0 = (const float*)d_in[4];
    const float* ws1 = (const float*)d_in[5];  const float* bs1 = (const float*)d_in[6];
    const float* ws2 = (const float*)d_in[7];  const float* bs2 = (const float*)d_in[8];
    const float* wsh = (const float*)d_in[9];  const float* bsh = (const float*)d_in[10];
    const float* wt0 = (const float*)d_in[11]; const float* bt0 = (const float*)d_in[12];
    const float* wt1 = (const float*)d_in[13]; const float* bt1 = (const float*)d_in[14];
    const float* wt2 = (const float*)d_in[15]; const float* bt2 = (const float*)d_in[16];
    float* out = (float*)d_out;

    int B   = in_sizes[1] / 64;
    int BHW = in_sizes[0] / 2;
    int HW  = BHW / B;

    prep_kernel<<<64, 256>>>(ws0, bs0, sc, ws1, ws2, wsh, wt0, bt0, tc, wt1, wt2, B);
    decoder_kernel<<<BHW / 64, 128>>>(coords, bs1, bs2, bsh, bt1, bt2, out, HW, BHW);
}

// round 12
// speedup vs baseline: 1.3048x; 1.3048x over previous
#include <cuda_runtime.h>
#include <math.h>

// SpritesAndTexturesCoordinateDecoder — bf16 split mma.sync decoder, v7.
// = R7 (516us) with lo-A fragments moved to thread-private SMEM slabs:
// frees 32 mandatory regs -> bigger ptxas scheduling window at 12 warps/SM.

typedef unsigned int u32;

__device__ __align__(16) uint4 g_Bfrag[5][4096];   // [layer][(ks*16+nt)*32+lane] {hiB0,hiB1,loB0,loB1}
__device__ float g_b0[8 * 128], g_bt0[8 * 128];
__device__ float g_swsh[128], g_swt2[384];

__device__ __forceinline__ float lrelu_s2(float v) {
    return fmaf(0.84852813742385703f, v, 0.56568542494923801f * fabsf(v));
}
__device__ __forceinline__ void my_sincos(float x, float* sp, float* cp) {
    float k = rintf(x * 0.63661977236758134f);
    int   q = (int)k;
    float r = fmaf(k, -1.5707963705062866f, x);
    r       = fmaf(k,  4.3711390001862456e-8f, r);
    float r2 = r * r;
    float p  = fmaf(r2, fmaf(r2, -1.9841271e-4f, 8.3333310e-3f), -1.6666667e-1f);
    float s  = fmaf(p * r2, r, r);
    float qq = fmaf(r2, fmaf(r2, 2.4801587e-5f, -1.3888889e-3f), 4.1666668e-2f);
    float c  = fmaf(qq * r2, r2, fmaf(r2, -0.5f, 1.f));
    int   qm = q & 3;
    float sv = (qm & 1) ? c : s;
    float cv = (qm & 1) ? s : c;
    if (qm == 1 || qm == 2) cv = -cv;
    if (qm == 2 || qm == 3) sv = -sv;
    *sp = sv; *cp = cv;
}
__device__ __forceinline__ u32 bfbits32(float v) {
    u32 r; asm("{ .reg .b16 h; cvt.rn.bf16.f32 h, %1; mov.b32 %0, {h, 0}; }" : "=r"(r) : "f"(v));
    return r & 0xFFFFu;
}
__device__ __forceinline__ void mma4(float* c, const u32* a, u32 b0, u32 b1) {
    asm("mma.sync.aligned.m16n8k16.row.col.f32.bf16.bf16.f32 "
        "{%0,%1,%2,%3}, {%4,%5,%6,%7}, {%8,%9}, {%0,%1,%2,%3};"
        : "+f"(c[0]), "+f"(c[1]), "+f"(c[2]), "+f"(c[3])
        : "r"(a[0]), "r"(a[1]), "r"(a[2]), "r"(a[3]), "r"(b0), "r"(b1));
}
__device__ __forceinline__ void split2(float v0, float v1, u32& hi, u32& lo) {
    u32 u0 = __float_as_uint(v0), u1 = __float_as_uint(v1);
    hi = __byte_perm(u0, u1, 0x7632);
    float l0 = v0 - __uint_as_float(u0 & 0xFFFF0000u);
    float l1 = v1 - __uint_as_float(u1 & 0xFFFF0000u);
    asm("cvt.rn.bf16x2.f32 %0, %1, %2;" : "=r"(lo) : "f"(l1), "f"(l0));
}

// lo slab per warp: u32[1024] = 4KB, record = ks*128 + lane*4 + reg.
// Thread-private addresses, plain C++ accesses -> compiler-ordered, no sync.

// MODE: 0 normal, 1 = L2 (shape partials), 2 = last (texture partials, no split)
template <int NKS, int MODE>
__device__ __forceinline__ void run_layer(const uint4* __restrict__ wfrag,
                                          const float* __restrict__ bias,
                                          u32 (&ah)[8][4], u32* slp,
                                          int lane, int q, float* hp)
{
    float acc[16][4];
#pragma unroll
    for (int nt = 0; nt < 16; nt++)
        acc[nt][0] = acc[nt][1] = acc[nt][2] = acc[nt][3] = 0.f;

    const uint4* wp = wfrag + lane;
#pragma unroll
    for (int ks = 0; ks < NKS; ks++) {
        uint4 alv = *(const uint4*)(slp + ks * 128);
        u32 alc[4] = { alv.x, alv.y, alv.z, alv.w };
#pragma unroll
        for (int g = 0; g < 4; g++) {
            int nt = g * 4;
            const uint4* p = wp + (ks * 16 + nt) * 32;
            uint4 fa = __ldg(p);
            uint4 fb = __ldg(p + 32);
            uint4 fc = __ldg(p + 64);
            uint4 fd = __ldg(p + 96);
            mma4(acc[nt],     ah[ks], fa.x, fa.y);
            mma4(acc[nt + 1], ah[ks], fb.x, fb.y);
            mma4(acc[nt + 2], ah[ks], fc.x, fc.y);
            mma4(acc[nt + 3], ah[ks], fd.x, fd.y);
            mma4(acc[nt],     ah[ks], fa.z, fa.w);
            mma4(acc[nt + 1], ah[ks], fb.z, fb.w);
            mma4(acc[nt + 2], ah[ks], fc.z, fc.w);
            mma4(acc[nt + 3], ah[ks], fd.z, fd.w);
            mma4(acc[nt],     alc, fa.x, fa.y);
            mma4(acc[nt + 1], alc, fb.x, fb.y);
            mma4(acc[nt + 2], alc, fc.x, fc.y);
            mma4(acc[nt + 3], alc, fd.x, fd.y);
        }
    }
#pragma unroll
    for (int nt = 0; nt < 16; nt++) {
        float2 b = __ldg((const float2*)(bias + nt * 8 + 2 * q));
        float v0 = lrelu_s2(acc[nt][0] + b.x), v1 = lrelu_s2(acc[nt][1] + b.y);
        float v2 = lrelu_s2(acc[nt][2] + b.x), v3 = lrelu_s2(acc[nt][3] + b.y);
        int ch = nt * 8 + 2 * q;
        if (MODE == 1) {
            float2 wv = __ldg((const float2*)(g_swsh + ch));
            hp[0] = fmaf(v0, wv.x, fmaf(v1, wv.y, hp[0]));
            hp[1] = fmaf(v2, wv.x, fmaf(v3, wv.y, hp[1]));
        }
        if (MODE == 2) {
#pragma unroll
            for (int c = 0; c < 3; c++) {
                float2 wv = __ldg((const float2*)(g_swt2 + c * 128 + ch));
                hp[2 * c]     = fmaf(v0, wv.x, fmaf(v1, wv.y, hp[2 * c]));
                hp[2 * c + 1] = fmaf(v2, wv.x, fmaf(v3, wv.y, hp[2 * c + 1]));
            }
        } else {
            int ks2 = nt >> 1, hf = nt & 1;
            u32 h0, l0, h1, l1;
            split2(v0, v1, h0, l0);
            split2(v2, v3, h1, l1);
            ah[ks2][2 * hf]     = h0;
            ah[ks2][2 * hf + 1] = h1;
            *(uint2*)(slp + ks2 * 128 + hf * 2) = make_uint2(l0, l1);
        }
    }
}

__global__ void prep_kernel(
    const float* __restrict__ ws0, const float* __restrict__ bs0, const float* __restrict__ sc,
    const float* __restrict__ ws1, const float* __restrict__ ws2, const float* __restrict__ wsh,
    const float* __restrict__ wt0, const float* __restrict__ bt0, const float* __restrict__ tc,
    const float* __restrict__ wt1, const float* __restrict__ wt2, int B)
{
    const float s0 = 1.f / sqrtf(96.f), s1 = 1.f / sqrtf(128.f), st0 = 1.f / sqrtf(192.f);
    int nth = blockDim.x * gridDim.x;
    int tid0 = blockIdx.x * blockDim.x + threadIdx.x;

    for (int l = 0; l < 5; l++) {
        int KS; const float* src; float scl; int srcw;
        if      (l == 0) { KS = 2; src = ws0; scl = s0;  srcw = 96;  }
        else if (l == 1) { KS = 8; src = ws1; scl = s1;  srcw = 128; }
        else if (l == 2) { KS = 8; src = ws2; scl = s1;  srcw = 128; }
        else if (l == 3) { KS = 8; src = wt0; scl = st0; srcw = 192; }
        else             { KS = 8; src = wt1; scl = s1;  srcw = 128; }
        int tot = KS * 512;
        for (int idx = tid0; idx < tot; idx += nth) {
            int ks = idx >> 9, rem = idx & 511, nt = rem >> 5, lane = rem & 31;
            int q = lane & 3, gg = lane >> 2;
            int n = nt * 8 + gg;
            int ka = ks * 16 + 2 * q;
            float w[4];
            w[0] = src[n * srcw + ka] * scl;
            w[1] = src[n * srcw + ka + 1] * scl;
            w[2] = src[n * srcw + ka + 8] * scl;
            w[3] = src[n * srcw + ka + 9] * scl;
            u32 h[4], lo[4];
            for (int i = 0; i < 4; i++) {
                u32 ub = __float_as_uint(w[i]) & 0xFFFF0000u;
                h[i] = ub >> 16;
                lo[i] = bfbits32(w[i] - __uint_as_float(ub));
            }
            uint4 f;
            f.x = h[0] | (h[1] << 16);
            f.y = h[2] | (h[3] << 16);
            f.z = lo[0] | (lo[1] << 16);
            f.w = lo[2] | (lo[3] << 16);
            g_Bfrag[l][(ks * 16 + nt) * 32 + lane] = f;
        }
    }
    for (int i = tid0; i < 128; i += nth) g_swsh[i] = wsh[i] * s1;
    for (int i = tid0; i < 384; i += nth) g_swt2[i] = wt2[i] * s1;
    for (int idx = tid0; idx < B * 128 && idx < 8 * 128; idx += nth) {
        int b = idx >> 7, j = idx & 127;
        float a = 0.f, t = 0.f;
        for (int m = 0; m < 64; m++) {
            a += sc[b * 64 + m] * ws0[j * 96 + 32 + m];
            t += tc[b * 64 + m] * wt0[j * 192 + 128 + m];
        }
        g_b0 [b * 128 + j] = bs0[j] + a * s0;
        g_bt0[b * 128 + j] = bt0[j] + t * st0;
    }
}

__global__ __launch_bounds__(128, 3)
void decoder_kernel(const float* __restrict__ coords,
                    const float* __restrict__ bs1, const float* __restrict__ bs2,
                    const float* __restrict__ bsh, const float* __restrict__ bt1,
                    const float* __restrict__ bt2,
                    float* __restrict__ out, int HW, int BHW)
{
    __shared__ __align__(16) u32 sLo[4][1024];   // 4 warps x 4KB (lo-A slabs)

    int tid = threadIdx.x;
    int lane = tid & 31, w = tid >> 5;
    int q = lane & 3, g = lane >> 2;
    int base = blockIdx.x * 64;          // 4 warps x 16 px
    int batch = base / HW;
    int px0 = base + w * 16 + g, px1 = px0 + 8;
    u32* slp = &sLo[w][lane * 4];

    float2 crd0 = __ldg(&((const float2*)coords)[px0]);
    float2 crd1 = __ldg(&((const float2*)coords)[px1]);

    // ---- embedding -> A fragments for L0 (K=32 => ksteps 0,1)
    u32 ah[8][4];
#pragma unroll
    for (int ks = 0; ks < 2; ks++) {
#pragma unroll
        for (int h = 0; h < 2; h++) {
            int s = 4 * ks + 2 * h + (q >> 1);
            float scl = 0.1f * (float)(1 << s);
#pragma unroll
            for (int row = 0; row < 2; row++) {
                float cx = (row ? crd1.x : crd0.x) * scl;
                float cy = (row ? crd1.y : crd0.y) * scl;
                float sx, cxv, sy, cyv;
                my_sincos(cx, &sx, &cxv);
                my_sincos(cy, &sy, &cyv);
                float v0 = (q & 1) ? cxv : sx;
                float v1 = (q & 1) ? cyv : sy;
                u32 hi, lo;
                split2(v0, v1, hi, lo);
                ah[ks][2 * h + row] = hi;
                slp[ks * 128 + 2 * h + row] = lo;
            }
        }
    }

    float dummy[1];
    run_layer<2, 0>(g_Bfrag[0], g_b0 + batch * 128, ah, slp, lane, q, dummy);   // L0
    run_layer<8, 0>(g_Bfrag[1], bs1,                ah, slp, lane, q, dummy);   // L1

    // L2 + shape head partials
    float pS[2] = {0.f, 0.f};
    run_layer<8, 1>(g_Bfrag[2], bs2, ah, slp, lane, q, pS);
    {
        pS[0] += __shfl_xor_sync(0xffffffffu, pS[0], 1);
        pS[0] += __shfl_xor_sync(0xffffffffu, pS[0], 2);
        pS[1] += __shfl_xor_sync(0xffffffffu, pS[1], 1);
        pS[1] += __shfl_xor_sync(0xffffffffu, pS[1], 2);
        if (q == 0) {
            float bv = __ldg(bsh);
            float r0 = sqrtf(crd0.x * crd0.x + crd0.y * crd0.y);
            float r1 = sqrtf(crd1.x * crd1.x + crd1.y * crd1.y);
            out[px0] = (pS[0] + bv) * (1.f - tanhf(fmaxf(r0 - 1.f, 0.f)));
            out[px1] = (pS[1] + bv) * (1.f - tanhf(fmaxf(r1 - 1.f, 0.f)));
        }
    }

    run_layer<8, 0>(g_Bfrag[3], g_bt0 + batch * 128, ah, slp, lane, q, dummy);  // T0

    // T1 + texture head partials
    float pT[6] = {0.f, 0.f, 0.f, 0.f, 0.f, 0.f};
    run_layer<8, 2>(g_Bfrag[4], bt1, ah, slp, lane, q, pT);
    {
#pragma unroll
        for (int i = 0; i < 6; i++) {
            pT[i] += __shfl_xor_sync(0xffffffffu, pT[i], 1);
            pT[i] += __shfl_xor_sync(0xffffffffu, pT[i], 2);
        }
        if (q == 0) {
            float* tp = out + BHW;
#pragma unroll
            for (int c = 0; c < 3; c++) {
                float bv = __ldg(bt2 + c);
                tp[3 * px0 + c] = pT[2 * c] + bv;
                tp[3 * px1 + c] = pT[2 * c + 1] + bv;
            }
        }
    }
}

extern "C" void kernel_launch(void* const* d_in, const int* in_sizes, int n_in,
                              void* d_out, int out_size)
{
    const float* coords = (const float*)d_in[0];
    const float* sc  = (const float*)d_in[1];
    const float* tc  = (const float*)d_in[2];
    const float* ws0 = (const float*)d_in[3];  const float* bs0 = (const float*)d_in[4];
    const float* ws1 = (const float*)d_in[5];  const float* bs1 = (const float*)d_in[6];
    const float* ws2 = (const float*)d_in[7];  const float* bs2 = (const float*)d_in[8];
    const float* wsh = (const float*)d_in[9];  const float* bsh = (const float*)d_in[10];
    const float* wt0 = (const float*)d_in[11]; const float* bt0 = (const float*)d_in[12];
    const float* wt1 = (const float*)d_in[13]; const float* bt1 = (const float*)d_in[14];
    const float* wt2 = (const float*)d_in[15]; const float* bt2 = (const float*)d_in[16];
    float* out = (float*)d_out;

    int B   = in_sizes[1] / 64;
    int BHW = in_sizes[0] / 2;
    int HW  = BHW / B;

    prep_kernel<<<64, 256>>>(ws0, bs0, sc, ws1, ws2, wsh, wt0, bt0, tc, wt1, wt2, B);
    decoder_kernel<<<BHW / 64, 128>>>(coords, bs1, bs2, bsh, bt1, bt2, out, HW, BHW);
}

// round 13
// speedup vs baseline: 1.3370x; 1.0247x over previous
#include <cuda_runtime.h>
#include <math.h>

// SpritesAndTexturesCoordinateDecoder — bf16 split mma.sync decoder, v8.
// Warp PAIRS: two warps share 16 pixels; each computes 64 of the 128 output
// channels (acc = 32 regs). Full A-fragments live in a pair-shared, double-
// buffered SMEM slab (1 __syncthreads per layer). Mandatory regs ~80 ->
// 16 warps/SM with real scheduling headroom.

typedef unsigned int u32;

__device__ __align__(16) uint4 g_Bfrag[5][4096];   // [(ks*16+gnt)*32+lane] {hiB0,hiB1,loB0,loB1}
__device__ float g_b0[8 * 128], g_bt0[8 * 128];
__device__ float g_swsh[128], g_swt2[384];

__device__ __forceinline__ float lrelu_s2(float v) {
    return fmaf(0.84852813742385703f, v, 0.56568542494923801f * fabsf(v));
}
__device__ __forceinline__ void my_sincos(float x, float* sp, float* cp) {
    float k = rintf(x * 0.63661977236758134f);
    int   q = (int)k;
    float r = fmaf(k, -1.5707963705062866f, x);
    r       = fmaf(k,  4.3711390001862456e-8f, r);
    float r2 = r * r;
    float p  = fmaf(r2, fmaf(r2, -1.9841271e-4f, 8.3333310e-3f), -1.6666667e-1f);
    float s  = fmaf(p * r2, r, r);
    float qq = fmaf(r2, fmaf(r2, 2.4801587e-5f, -1.3888889e-3f), 4.1666668e-2f);
    float c  = fmaf(qq * r2, r2, fmaf(r2, -0.5f, 1.f));
    int   qm = q & 3;
    float sv = (qm & 1) ? c : s;
    float cv = (qm & 1) ? s : c;
    if (qm == 1 || qm == 2) cv = -cv;
    if (qm == 2 || qm == 3) sv = -sv;
    *sp = sv; *cp = cv;
}
__device__ __forceinline__ u32 bfbits32(float v) {
    u32 r; asm("{ .reg .b16 h; cvt.rn.bf16.f32 h, %1; mov.b32 %0, {h, 0}; }" : "=r"(r) : "f"(v));
    return r & 0xFFFFu;
}
__device__ __forceinline__ void mma4(float* c, const u32* a, u32 b0, u32 b1) {
    asm("mma.sync.aligned.m16n8k16.row.col.f32.bf16.bf16.f32 "
        "{%0,%1,%2,%3}, {%4,%5,%6,%7}, {%8,%9}, {%0,%1,%2,%3};"
        : "+f"(c[0]), "+f"(c[1]), "+f"(c[2]), "+f"(c[3])
        : "r"(a[0]), "r"(a[1]), "r"(a[2]), "r"(a[3]), "r"(b0), "r"(b1));
}
__device__ __forceinline__ void split2(float v0, float v1, u32& hi, u32& lo) {
    u32 u0 = __float_as_uint(v0), u1 = __float_as_uint(v1);
    hi = __byte_perm(u0, u1, 0x7632);
    float l0 = v0 - __uint_as_float(u0 & 0xFFFF0000u);
    float l1 = v1 - __uint_as_float(u1 & 0xFFFF0000u);
    asm("cvt.rn.bf16x2.f32 %0, %1, %2;" : "=r"(lo) : "f"(l1), "f"(l0));
}

// Pair slab buffer: u32[2048] = 8KB. hi: [ks*128 + lane*4 + reg], lo: +1024.

// MODE: 0 normal, 1 = L2 (shape partials + A-write), 2 = last (texture partials)
template <int NKS, int MODE>
__device__ __forceinline__ void run_layer(const uint4* __restrict__ wfrag,
                                          const float* __restrict__ bias,
                                          const u32* rbuf, u32* wbuf,
                                          int lane, int q, int half, float* hp)
{
    float acc[8][4];
#pragma unroll
    for (int nt = 0; nt < 8; nt++)
        acc[nt][0] = acc[nt][1] = acc[nt][2] = acc[nt][3] = 0.f;

#pragma unroll
    for (int ks = 0; ks < NKS; ks++) {
        uint4 ahv = *(const uint4*)(rbuf + ks * 128 + lane * 4);
        uint4 alv = *(const uint4*)(rbuf + 1024 + ks * 128 + lane * 4);
        u32 ahc[4] = { ahv.x, ahv.y, ahv.z, ahv.w };
        u32 alc[4] = { alv.x, alv.y, alv.z, alv.w };
#pragma unroll
        for (int grp = 0; grp < 2; grp++) {
            int nt = grp * 4;
            const uint4* p = wfrag + (ks * 16 + half * 8 + nt) * 32 + lane;
            uint4 fa = __ldg(p);
            uint4 fb = __ldg(p + 32);
            uint4 fc = __ldg(p + 64);
            uint4 fd = __ldg(p + 96);
            mma4(acc[nt],     ahc, fa.x, fa.y);
            mma4(acc[nt + 1], ahc, fb.x, fb.y);
            mma4(acc[nt + 2], ahc, fc.x, fc.y);
            mma4(acc[nt + 3], ahc, fd.x, fd.y);
            mma4(acc[nt],     ahc, fa.z, fa.w);
            mma4(acc[nt + 1], ahc, fb.z, fb.w);
            mma4(acc[nt + 2], ahc, fc.z, fc.w);
            mma4(acc[nt + 3], ahc, fd.z, fd.w);
            mma4(acc[nt],     alc, fa.x, fa.y);
            mma4(acc[nt + 1], alc, fb.x, fb.y);
            mma4(acc[nt + 2], alc, fc.x, fc.y);
            mma4(acc[nt + 3], alc, fd.x, fd.y);
        }
    }
#pragma unroll
    for (int nt = 0; nt < 8; nt++) {
        int gnt = half * 8 + nt;
        float2 b = __ldg((const float2*)(bias + gnt * 8 + 2 * q));
        float v0 = lrelu_s2(acc[nt][0] + b.x), v1 = lrelu_s2(acc[nt][1] + b.y);
        float v2 = lrelu_s2(acc[nt][2] + b.x), v3 = lrelu_s2(acc[nt][3] + b.y);
        int ch = gnt * 8 + 2 * q;
        if (MODE == 1) {
            float2 wv = __ldg((const float2*)(g_swsh + ch));
            hp[0] = fmaf(v0, wv.x, fmaf(v1, wv.y, hp[0]));
            hp[1] = fmaf(v2, wv.x, fmaf(v3, wv.y, hp[1]));
        }
        if (MODE == 2) {
#pragma unroll
            for (int c = 0; c < 3; c++) {
                float2 wv = __ldg((const float2*)(g_swt2 + c * 128 + ch));
                hp[2 * c]     = fmaf(v0, wv.x, fmaf(v1, wv.y, hp[2 * c]));
                hp[2 * c + 1] = fmaf(v2, wv.x, fmaf(v3, wv.y, hp[2 * c + 1]));
            }
        } else {
            int ks2 = gnt >> 1, hf = gnt & 1;
            u32 h0, l0, h1, l1;
            split2(v0, v1, h0, l0);
            split2(v2, v3, h1, l1);
            *(uint2*)(wbuf + ks2 * 128 + lane * 4 + hf * 2)        = make_uint2(h0, h1);
            *(uint2*)(wbuf + 1024 + ks2 * 128 + lane * 4 + hf * 2) = make_uint2(l0, l1);
        }
    }
}

__global__ void prep_kernel(
    const float* __restrict__ ws0, const float* __restrict__ bs0, const float* __restrict__ sc,
    const float* __restrict__ ws1, const float* __restrict__ ws2, const float* __restrict__ wsh,
    const float* __restrict__ wt0, const float* __restrict__ bt0, const float* __restrict__ tc,
    const float* __restrict__ wt1, const float* __restrict__ wt2, int B)
{
    const float s0 = 1.f / sqrtf(96.f), s1 = 1.f / sqrtf(128.f), st0 = 1.f / sqrtf(192.f);
    int nth = blockDim.x * gridDim.x;
    int tid0 = blockIdx.x * blockDim.x + threadIdx.x;

    for (int l = 0; l < 5; l++) {
        int KS; const float* src; float scl; int srcw;
        if      (l == 0) { KS = 2; src = ws0; scl = s0;  srcw = 96;  }
        else if (l == 1) { KS = 8; src = ws1; scl = s1;  srcw = 128; }
        else if (l == 2) { KS = 8; src = ws2; scl = s1;  srcw = 128; }
        else if (l == 3) { KS = 8; src = wt0; scl = st0; srcw = 192; }
        else             { KS = 8; src = wt1; scl = s1;  srcw = 128; }
        int tot = KS * 512;
        for (int idx = tid0; idx < tot; idx += nth) {
            int ks = idx >> 9, rem = idx & 511, nt = rem >> 5, lane = rem & 31;
            int q = lane & 3, gg = lane >> 2;
            int n = nt * 8 + gg;
            int ka = ks * 16 + 2 * q;
            float w[4];
            w[0] = src[n * srcw + ka] * scl;
            w[1] = src[n * srcw + ka + 1] * scl;
            w[2] = src[n * srcw + ka + 8] * scl;
            w[3] = src[n * srcw + ka + 9] * scl;
            u32 h[4], lo[4];
            for (int i = 0; i < 4; i++) {
                u32 ub = __float_as_uint(w[i]) & 0xFFFF0000u;
                h[i] = ub >> 16;
                lo[i] = bfbits32(w[i] - __uint_as_float(ub));
            }
            uint4 f;
            f.x = h[0] | (h[1] << 16);
            f.y = h[2] | (h[3] << 16);
            f.z = lo[0] | (lo[1] << 16);
            f.w = lo[2] | (lo[3] << 16);
            g_Bfrag[l][(ks * 16 + nt) * 32 + lane] = f;
        }
    }
    for (int i = tid0; i < 128; i += nth) g_swsh[i] = wsh[i] * s1;
    for (int i = tid0; i < 384; i += nth) g_swt2[i] = wt2[i] * s1;
    for (int idx = tid0; idx < B * 128 && idx < 8 * 128; idx += nth) {
        int b = idx >> 7, j = idx & 127;
        float a = 0.f, t = 0.f;
        for (int m = 0; m < 64; m++) {
            a += sc[b * 64 + m] * ws0[j * 96 + 32 + m];
            t += tc[b * 64 + m] * wt0[j * 192 + 128 + m];
        }
        g_b0 [b * 128 + j] = bs0[j] + a * s0;
        g_bt0[b * 128 + j] = bt0[j] + t * st0;
    }
}

__global__ __launch_bounds__(128, 4)
void decoder_kernel(const float* __restrict__ coords,
                    const float* __restrict__ bs1, const float* __restrict__ bs2,
                    const float* __restrict__ bsh, const float* __restrict__ bt1,
                    const float* __restrict__ bt2,
                    float* __restrict__ out, int HW, int BHW)
{
    __shared__ __align__(16) u32   sA[2][2][2048];   // [pair][buf] 8KB slabs
    __shared__ float sH[2][2][8][8];                 // head partials [pair][half][g][ch]

    int tid = threadIdx.x;
    int lane = tid & 31, w = tid >> 5;
    int pair = w >> 1, half = w & 1;
    int q = lane & 3, g = lane >> 2;
    int base = blockIdx.x * 32;          // 2 pairs x 16 px
    int batch = base / HW;
    int px0 = base + pair * 16 + g, px1 = px0 + 8;

    u32* buf0 = &sA[pair][0][0];
    u32* buf1 = &sA[pair][1][0];

    float2 crd0 = __ldg(&((const float2*)coords)[px0]);
    float2 crd1 = __ldg(&((const float2*)coords)[px1]);

    // ---- embedding -> A fragments for L0 into buf0; this warp fills ks = half
    {
        int ks = half;
#pragma unroll
        for (int h = 0; h < 2; h++) {
            int s = 4 * ks + 2 * h + (q >> 1);
            float scl = 0.1f * (float)(1 << s);
#pragma unroll
            for (int row = 0; row < 2; row++) {
                float cx = (row ? crd1.x : crd0.x) * scl;
                float cy = (row ? crd1.y : crd0.y) * scl;
                float sx, cxv, sy, cyv;
                my_sincos(cx, &sx, &cxv);
                my_sincos(cy, &sy, &cyv);
                float v0 = (q & 1) ? cxv : sx;
                float v1 = (q & 1) ? cyv : sy;
                u32 hi, lo;
                split2(v0, v1, hi, lo);
                buf0[ks * 128 + lane * 4 + 2 * h + row]        = hi;
                buf0[1024 + ks * 128 + lane * 4 + 2 * h + row] = lo;
            }
        }
    }
    __syncthreads();

    float dummy[1];
    run_layer<2, 0>(g_Bfrag[0], g_b0 + batch * 128, buf0, buf1, lane, q, half, dummy);  // L0
    __syncthreads();
    run_layer<8, 0>(g_Bfrag[1], bs1, buf1, buf0, lane, q, half, dummy);                 // L1
    __syncthreads();

    // L2 + shape head partials (over this warp's 64 channels)
    float pS[2] = {0.f, 0.f};
    run_layer<8, 1>(g_Bfrag[2], bs2, buf0, buf1, lane, q, half, pS);
    pS[0] += __shfl_xor_sync(0xffffffffu, pS[0], 1);
    pS[0] += __shfl_xor_sync(0xffffffffu, pS[0], 2);
    pS[1] += __shfl_xor_sync(0xffffffffu, pS[1], 1);
    pS[1] += __shfl_xor_sync(0xffffffffu, pS[1], 2);
    if (q == 0) { sH[pair][half][g][0] = pS[0]; sH[pair][half][g][1] = pS[1]; }
    __syncthreads();

    if (half == 0 && q == 0) {
        float bv = __ldg(bsh);
        float s0v = sH[pair][0][g][0] + sH[pair][1][g][0] + bv;
        float s1v = sH[pair][0][g][1] + sH[pair][1][g][1] + bv;
        float r0 = sqrtf(crd0.x * crd0.x + crd0.y * crd0.y);
        float r1 = sqrtf(crd1.x * crd1.x + crd1.y * crd1.y);
        out[px0] = s0v * (1.f - tanhf(fmaxf(r0 - 1.f, 0.f)));
        out[px1] = s1v * (1.f - tanhf(fmaxf(r1 - 1.f, 0.f)));
    }

    run_layer<8, 0>(g_Bfrag[3], g_bt0 + batch * 128, buf1, buf0, lane, q, half, dummy); // T0
    __syncthreads();

    // T1 + texture head partials
    float pT[6] = {0.f, 0.f, 0.f, 0.f, 0.f, 0.f};
    run_layer<8, 2>(g_Bfrag[4], bt1, buf0, buf1, lane, q, half, pT);
#pragma unroll
    for (int i = 0; i < 6; i++) {
        pT[i] += __shfl_xor_sync(0xffffffffu, pT[i], 1);
        pT[i] += __shfl_xor_sync(0xffffffffu, pT[i], 2);
    }
    if (q == 0) {
#pragma unroll
        for (int i = 0; i < 6; i++) sH[pair][half][g][i] = pT[i];
    }
    __syncthreads();

    if (half == 0 && q == 0) {
        float* tp = out + BHW;
#pragma unroll
        for (int c = 0; c < 3; c++) {
            float bv = __ldg(bt2 + c);
            tp[3 * px0 + c] = sH[pair][0][g][2 * c]     + sH[pair][1][g][2 * c]     + bv;
            tp[3 * px1 + c] = sH[pair][0][g][2 * c + 1] + sH[pair][1][g][2 * c + 1] + bv;
        }
    }
}

extern "C" void kernel_launch(void* const* d_in, const int* in_sizes, int n_in,
                              void* d_out, int out_size)
{
    const float* coords = (const float*)d_in[0];
    const float* sc  = (const float*)d_in[1];
    const float* tc  = (const float*)d_in[2];
    const float* ws0 = (const float*)d_in[3];  const float* bs0 = (const float*)d_in[4];
    const float* ws1 = (const float*)d_in[5];  const float* bs1 = (const float*)d_in[6];
    const float* ws2 = (const float*)d_in[7];  const float* bs2 = (const float*)d_in[8];
    const float* wsh = (const float*)d_in[9];  const float* bsh = (const float*)d_in[10];
    const float* wt0 = (const float*)d_in[11]; const float* bt0 = (const float*)d_in[12];
    const float* wt1 = (const float*)d_in[13]; const float* bt1 = (const float*)d_in[14];
    const float* wt2 = (const float*)d_in[15]; const float* bt2 = (const float*)d_in[16];
    float* out = (float*)d_out;

    int B   = in_sizes[1] / 64;
    int BHW = in_sizes[0] / 2;
    int HW  = BHW / B;

    prep_kernel<<<64, 256>>>(ws0, bs0, sc, ws1, ws2, wsh, wt0, bt0, tc, wt1, wt2, B);
    decoder_kernel<<<BHW / 32, 128>>>(coords, bs1, bs2, bsh, bt1, bt2, out, HW, BHW);
}

// round 14
// speedup vs baseline: 1.3929x; 1.0419x over previous
#include <cuda_runtime.h>
#include <math.h>

// SpritesAndTexturesCoordinateDecoder — bf16 split mma.sync decoder, v9.
// Quad scheme: CTA = 4 warps = 32 pixels. Each warp: 32 output channels x
// 32 pixels (2 A-tiles) -> every B-fragment LDG feeds 6 MMAs (was 3).
// A-fragments in a CTA-shared double-buffered slab; 1 sync per layer.

typedef unsigned int u32;

__device__ __align__(16) uint4 g_Bfrag[5][4096];   // [(ks*16+gnt)*32+lane] {hiB0,hiB1,loB0,loB1}
__device__ float g_b0[8 * 128], g_bt0[8 * 128];
__device__ float g_swsh[128], g_swt2[384];

__device__ __forceinline__ float lrelu_s2(float v) {
    return fmaf(0.84852813742385703f, v, 0.56568542494923801f * fabsf(v));
}
__device__ __forceinline__ void my_sincos(float x, float* sp, float* cp) {
    float k = rintf(x * 0.63661977236758134f);
    int   q = (int)k;
    float r = fmaf(k, -1.5707963705062866f, x);
    r       = fmaf(k,  4.3711390001862456e-8f, r);
    float r2 = r * r;
    float p  = fmaf(r2, fmaf(r2, -1.9841271e-4f, 8.3333310e-3f), -1.6666667e-1f);
    float s  = fmaf(p * r2, r, r);
    float qq = fmaf(r2, fmaf(r2, 2.4801587e-5f, -1.3888889e-3f), 4.1666668e-2f);
    float c  = fmaf(qq * r2, r2, fmaf(r2, -0.5f, 1.f));
    int   qm = q & 3;
    float sv = (qm & 1) ? c : s;
    float cv = (qm & 1) ? s : c;
    if (qm == 1 || qm == 2) cv = -cv;
    if (qm == 2 || qm == 3) sv = -sv;
    *sp = sv; *cp = cv;
}
__device__ __forceinline__ u32 bfbits32(float v) {
    u32 r; asm("{ .reg .b16 h; cvt.rn.bf16.f32 h, %1; mov.b32 %0, {h, 0}; }" : "=r"(r) : "f"(v));
    return r & 0xFFFFu;
}
__device__ __forceinline__ void mma4(float* c, const u32* a, u32 b0, u32 b1) {
    asm("mma.sync.aligned.m16n8k16.row.col.f32.bf16.bf16.f32 "
        "{%0,%1,%2,%3}, {%4,%5,%6,%7}, {%8,%9}, {%0,%1,%2,%3};"
        : "+f"(c[0]), "+f"(c[1]), "+f"(c[2]), "+f"(c[3])
        : "r"(a[0]), "r"(a[1]), "r"(a[2]), "r"(a[3]), "r"(b0), "r"(b1));
}
__device__ __forceinline__ void split2(float v0, float v1, u32& hi, u32& lo) {
    u32 u0 = __float_as_uint(v0), u1 = __float_as_uint(v1);
    hi = __byte_perm(u0, u1, 0x7632);
    float l0 = v0 - __uint_as_float(u0 & 0xFFFF0000u);
    float l1 = v1 - __uint_as_float(u1 & 0xFFFF0000u);
    asm("cvt.rn.bf16x2.f32 %0, %1, %2;" : "=r"(lo) : "f"(l1), "f"(l0));
}

// Slab (per CTA): u32[2][4096]. Within a buf: hi plane [0,2048), lo plane [2048,4096).
// record = (tile*8 + ks)*128 + lane*4 + reg.

// MODE: 0 normal, 1 = L2 (shape partials + A-write), 2 = last (texture partials)
// hp: MODE1 -> 4 floats [tile*2+row]; MODE2 -> 12 floats [tile*6 + c*2 + row]
template <int NKS, int MODE>
__device__ __forceinline__ void run_layer(const uint4* __restrict__ wfrag,
                                          const float* __restrict__ bias,
                                          const u32* rbuf, u32* wbuf,
                                          int lane, int q, int w, float* hp)
{
    float acc[2][4][4];   // [tile][nt][reg]
#pragma unroll
    for (int t = 0; t < 2; t++)
#pragma unroll
        for (int nt = 0; nt < 4; nt++)
            acc[t][nt][0] = acc[t][nt][1] = acc[t][nt][2] = acc[t][nt][3] = 0.f;

#pragma unroll
    for (int ks = 0; ks < NKS; ks++) {
        uint4 h0v = *(const uint4*)(rbuf + (0 * 8 + ks) * 128 + lane * 4);
        uint4 l0v = *(const uint4*)(rbuf + 2048 + (0 * 8 + ks) * 128 + lane * 4);
        uint4 h1v = *(const uint4*)(rbuf + (1 * 8 + ks) * 128 + lane * 4);
        uint4 l1v = *(const uint4*)(rbuf + 2048 + (1 * 8 + ks) * 128 + lane * 4);
        u32 ah0[4] = { h0v.x, h0v.y, h0v.z, h0v.w };
        u32 al0[4] = { l0v.x, l0v.y, l0v.z, l0v.w };
        u32 ah1[4] = { h1v.x, h1v.y, h1v.z, h1v.w };
        u32 al1[4] = { l1v.x, l1v.y, l1v.z, l1v.w };
        const uint4* p = wfrag + (ks * 16 + w * 4) * 32 + lane;
        uint4 f0 = __ldg(p);
        uint4 f1 = __ldg(p + 32);
        uint4 f2 = __ldg(p + 64);
        uint4 f3 = __ldg(p + 96);
#pragma unroll
        for (int nt = 0; nt < 4; nt++) {
            uint4 f = (nt == 0) ? f0 : (nt == 1) ? f1 : (nt == 2) ? f2 : f3;
            mma4(acc[0][nt], ah0, f.x, f.y);
            mma4(acc[1][nt], ah1, f.x, f.y);
            mma4(acc[0][nt], ah0, f.z, f.w);
            mma4(acc[1][nt], ah1, f.z, f.w);
            mma4(acc[0][nt], al0, f.x, f.y);
            mma4(acc[1][nt], al1, f.x, f.y);
        }
    }
#pragma unroll
    for (int t = 0; t < 2; t++) {
#pragma unroll
        for (int nt = 0; nt < 4; nt++) {
            int gnt = w * 4 + nt;
            float2 b = __ldg((const float2*)(bias + gnt * 8 + 2 * q));
            float v0 = lrelu_s2(acc[t][nt][0] + b.x), v1 = lrelu_s2(acc[t][nt][1] + b.y);
            float v2 = lrelu_s2(acc[t][nt][2] + b.x), v3 = lrelu_s2(acc[t][nt][3] + b.y);
            int ch = gnt * 8 + 2 * q;
            if (MODE == 1) {
                float2 wv = __ldg((const float2*)(g_swsh + ch));
                hp[t * 2 + 0] = fmaf(v0, wv.x, fmaf(v1, wv.y, hp[t * 2 + 0]));
                hp[t * 2 + 1] = fmaf(v2, wv.x, fmaf(v3, wv.y, hp[t * 2 + 1]));
            }
            if (MODE == 2) {
#pragma unroll
                for (int c = 0; c < 3; c++) {
                    float2 wv = __ldg((const float2*)(g_swt2 + c * 128 + ch));
                    hp[t * 6 + c * 2 + 0] = fmaf(v0, wv.x, fmaf(v1, wv.y, hp[t * 6 + c * 2 + 0]));
                    hp[t * 6 + c * 2 + 1] = fmaf(v2, wv.x, fmaf(v3, wv.y, hp[t * 6 + c * 2 + 1]));
                }
            } else {
                int ks2 = gnt >> 1, hf = gnt & 1;
                u32 h0, l0, h1, l1;
                split2(v0, v1, h0, l0);
                split2(v2, v3, h1, l1);
                *(uint2*)(wbuf + (t * 8 + ks2) * 128 + lane * 4 + hf * 2)        = make_uint2(h0, h1);
                *(uint2*)(wbuf + 2048 + (t * 8 + ks2) * 128 + lane * 4 + hf * 2) = make_uint2(l0, l1);
            }
        }
    }
}

__global__ void prep_kernel(
    const float* __restrict__ ws0, const float* __restrict__ bs0, const float* __restrict__ sc,
    const float* __restrict__ ws1, const float* __restrict__ ws2, const float* __restrict__ wsh,
    const float* __restrict__ wt0, const float* __restrict__ bt0, const float* __restrict__ tc,
    const float* __restrict__ wt1, const float* __restrict__ wt2, int B)
{
    const float s0 = 1.f / sqrtf(96.f), s1 = 1.f / sqrtf(128.f), st0 = 1.f / sqrtf(192.f);
    int nth = blockDim.x * gridDim.x;
    int tid0 = blockIdx.x * blockDim.x + threadIdx.x;

    for (int l = 0; l < 5; l++) {
        int KS; const float* src; float scl; int srcw;
        if      (l == 0) { KS = 2; src = ws0; scl = s0;  srcw = 96;  }
        else if (l == 1) { KS = 8; src = ws1; scl = s1;  srcw = 128; }
        else if (l == 2) { KS = 8; src = ws2; scl = s1;  srcw = 128; }
        else if (l == 3) { KS = 8; src = wt0; scl = st0; srcw = 192; }
        else             { KS = 8; src = wt1; scl = s1;  srcw = 128; }
        int tot = KS * 512;
        for (int idx = tid0; idx < tot; idx += nth) {
            int ks = idx >> 9, rem = idx & 511, nt = rem >> 5, lane = rem & 31;
            int q = lane & 3, gg = lane >> 2;
            int n = nt * 8 + gg;
            int ka = ks * 16 + 2 * q;
            float w[4];
            w[0] = src[n * srcw + ka] * scl;
            w[1] = src[n * srcw + ka + 1] * scl;
            w[2] = src[n * srcw + ka + 8] * scl;
            w[3] = src[n * srcw + ka + 9] * scl;
            u32 h[4], lo[4];
            for (int i = 0; i < 4; i++) {
                u32 ub = __float_as_uint(w[i]) & 0xFFFF0000u;
                h[i] = ub >> 16;
                lo[i] = bfbits32(w[i] - __uint_as_float(ub));
            }
            uint4 f;
            f.x = h[0] | (h[1] << 16);
            f.y = h[2] | (h[3] << 16);
            f.z = lo[0] | (lo[1] << 16);
            f.w = lo[2] | (lo[3] << 16);
            g_Bfrag[l][(ks * 16 + nt) * 32 + lane] = f;
        }
    }
    for (int i = tid0; i < 128; i += nth) g_swsh[i] = wsh[i] * s1;
    for (int i = tid0; i < 384; i += nth) g_swt2[i] = wt2[i] * s1;
    for (int idx = tid0; idx < B * 128 && idx < 8 * 128; idx += nth) {
        int b = idx >> 7, j = idx & 127;
        float a = 0.f, t = 0.f;
        for (int m = 0; m < 64; m++) {
            a += sc[b * 64 + m] * ws0[j * 96 + 32 + m];
            t += tc[b * 64 + m] * wt0[j * 192 + 128 + m];
        }
        g_b0 [b * 128 + j] = bs0[j] + a * s0;
        g_bt0[b * 128 + j] = bt0[j] + t * st0;
    }
}

__global__ __launch_bounds__(128, 4)
void decoder_kernel(const float* __restrict__ coords,
                    const float* __restrict__ bs1, const float* __restrict__ bs2,
                    const float* __restrict__ bsh, const float* __restrict__ bt1,
                    const float* __restrict__ bt2,
                    float* __restrict__ out, int HW, int BHW)
{
    __shared__ __align__(16) u32 sA[2][4096];   // double-buffered A slab (hi/lo planes)
    __shared__ float sHd[4][2][8][6];           // head partials [warp][tile][g][val]

    int tid = threadIdx.x;
    int lane = tid & 31, w = tid >> 5;
    int q = lane & 3, g = lane >> 2;
    int base = blockIdx.x * 32;
    int batch = base / HW;

    // ---- embedding: warp w fills (tile = w>>1, ks = w&1) of buf0
    {
        int tw = w >> 1, ks0 = w & 1;
        float2 crd0 = __ldg(&((const float2*)coords)[base + tw * 16 + g]);
        float2 crd1 = __ldg(&((const float2*)coords)[base + tw * 16 + g + 8]);
#pragma unroll
        for (int h = 0; h < 2; h++) {
            int s = 4 * ks0 + 2 * h + (q >> 1);
            float scl = 0.1f * (float)(1 << s);
#pragma unroll
            for (int row = 0; row < 2; row++) {
                float cx = (row ? crd1.x : crd0.x) * scl;
                float cy = (row ? crd1.y : crd0.y) * scl;
                float sx, cxv, sy, cyv;
                my_sincos(cx, &sx, &cxv);
                my_sincos(cy, &sy, &cyv);
                float v0 = (q & 1) ? cxv : sx;
                float v1 = (q & 1) ? cyv : sy;
                u32 hi, lo;
                split2(v0, v1, hi, lo);
                sA[0][(tw * 8 + ks0) * 128 + lane * 4 + 2 * h + row]        = hi;
                sA[0][2048 + (tw * 8 + ks0) * 128 + lane * 4 + 2 * h + row] = lo;
            }
        }
    }
    __syncthreads();

    float dummy[1];
    run_layer<2, 0>(g_Bfrag[0], g_b0 + batch * 128, sA[0], sA[1], lane, q, w, dummy);  // L0
    __syncthreads();
    run_layer<8, 0>(g_Bfrag[1], bs1, sA[1], sA[0], lane, q, w, dummy);                 // L1
    __syncthreads();

    // L2 + shape head partials (this warp's 32 channels, both tiles)
    float pS[4] = {0.f, 0.f, 0.f, 0.f};
    run_layer<8, 1>(g_Bfrag[2], bs2, sA[0], sA[1], lane, q, w, pS);
#pragma unroll
    for (int i = 0; i < 4; i++) {
        pS[i] += __shfl_xor_sync(0xffffffffu, pS[i], 1);
        pS[i] += __shfl_xor_sync(0xffffffffu, pS[i], 2);
    }
    if (q == 0) {
        sHd[w][0][g][0] = pS[0]; sHd[w][0][g][1] = pS[1];
        sHd[w][1][g][0] = pS[2]; sHd[w][1][g][1] = pS[3];
    }
    __syncthreads();   // also publishes L2's A-writes (sA[1]) for T0

    if (w < 2 && q == 0) {
        int px0 = base + w * 16 + g, px1 = px0 + 8;
        float bv = __ldg(bsh);
        float s0v = sHd[0][w][g][0] + sHd[1][w][g][0] + sHd[2][w][g][0] + sHd[3][w][g][0] + bv;
        float s1v = sHd[0][w][g][1] + sHd[1][w][g][1] + sHd[2][w][g][1] + sHd[3][w][g][1] + bv;
        float2 c0 = __ldg(&((const float2*)coords)[px0]);
        float2 c1 = __ldg(&((const float2*)coords)[px1]);
        float r0 = sqrtf(c0.x * c0.x + c0.y * c0.y);
        float r1 = sqrtf(c1.x * c1.x + c1.y * c1.y);
        out[px0] = s0v * (1.f - tanhf(fmaxf(r0 - 1.f, 0.f)));
        out[px1] = s1v * (1.f - tanhf(fmaxf(r1 - 1.f, 0.f)));
    }

    run_layer<8, 0>(g_Bfrag[3], g_bt0 + batch * 128, sA[1], sA[0], lane, q, w, dummy); // T0
    __syncthreads();

    // T1 + texture head partials
    float pT[12] = {0.f};
    run_layer<8, 2>(g_Bfrag[4], bt1, sA[0], sA[1], lane, q, w, pT);
#pragma unroll
    for (int i = 0; i < 12; i++) {
        pT[i] += __shfl_xor_sync(0xffffffffu, pT[i], 1);
        pT[i] += __shfl_xor_sync(0xffffffffu, pT[i], 2);
    }
    if (q == 0) {
#pragma unroll
        for (int t = 0; t < 2; t++)
#pragma unroll
            for (int i = 0; i < 6; i++) sHd[w][t][g][i] = pT[t * 6 + i];
    }
    __syncthreads();

    if (w < 2 && q == 0) {
        int px0 = base + w * 16 + g, px1 = px0 + 8;
        float* tp = out + BHW;
#pragma unroll
        for (int c = 0; c < 3; c++) {
            float bv = __ldg(bt2 + c);
            float t0v = sHd[0][w][g][2 * c]     + sHd[1][w][g][2 * c]     + sHd[2][w][g][2 * c]     + sHd[3][w][g][2 * c]     + bv;
            float t1v = sHd[0][w][g][2 * c + 1] + sHd[1][w][g][2 * c + 1] + sHd[2][w][g][2 * c + 1] + sHd[3][w][g][2 * c + 1] + bv;
            tp[3 * px0 + c] = t0v;
            tp[3 * px1 + c] = t1v;
        }
    }
}

extern "C" void kernel_launch(void* const* d_in, const int* in_sizes, int n_in,
                              void* d_out, int out_size)
{
    const float* coords = (const float*)d_in[0];
    const float* sc  = (const float*)d_in[1];
    const float* tc  = (const float*)d_in[2];
    const float* ws0 = (const float*)d_in[3];  const float* bs0 = (const float*)d_in[4];
    const float* ws1 = (const float*)d_in[5];  const float* bs1 = (const float*)d_in[6];
    const float* ws2 = (const float*)d_in[7];  const float* bs2 = (const float*)d_in[8];
    const float* wsh = (const float*)d_in[9];  const float* bsh = (const float*)d_in[10];
    const float* wt0 = (const float*)d_in[11]; const float* bt0 = (const float*)d_in[12];
    const float* wt1 = (const float*)d_in[13]; const float* bt1 = (const float*)d_in[14];
    const float* wt2 = (const float*)d_in[15]; const float* bt2 = (const float*)d_in[16];
    float* out = (float*)d_out;

    int B   = in_sizes[1] / 64;
    int BHW = in_sizes[0] / 2;
    int HW  = BHW / B;

    prep_kernel<<<64, 256>>>(ws0, bs0, sc, ws1, ws2, wsh, wt0, bt0, tc, wt1, wt2, B);
    decoder_kernel<<<BHW / 32, 128>>>(coords, bs1, bs2, bsh, bt1, bt2, out, HW, BHW);
}

// round 15
// speedup vs baseline: 1.4156x; 1.0163x over previous
#include <cuda_runtime.h>
#include <math.h>

// SpritesAndTexturesCoordinateDecoder — bf16 split mma.sync decoder, v10.
// = v9 quad scheme (CTA = 4 warps = 32 px; warp = 32ch x 32px; CTA-shared
// double-buffered A slab) with occupancy pushed to 5 CTAs/SM (20 warps):
// __launch_bounds__(128,5) -> ptxas reg target 102 (mandatory state ~90).

typedef unsigned int u32;

__device__ __align__(16) uint4 g_Bfrag[5][4096];   // [(ks*16+gnt)*32+lane] {hiB0,hiB1,loB0,loB1}
__device__ float g_b0[8 * 128], g_bt0[8 * 128];
__device__ float g_swsh[128], g_swt2[384];

__device__ __forceinline__ float lrelu_s2(float v) {
    return fmaf(0.84852813742385703f, v, 0.56568542494923801f * fabsf(v));
}
__device__ __forceinline__ void my_sincos(float x, float* sp, float* cp) {
    float k = rintf(x * 0.63661977236758134f);
    int   q = (int)k;
    float r = fmaf(k, -1.5707963705062866f, x);
    r       = fmaf(k,  4.3711390001862456e-8f, r);
    float r2 = r * r;
    float p  = fmaf(r2, fmaf(r2, -1.9841271e-4f, 8.3333310e-3f), -1.6666667e-1f);
    float s  = fmaf(p * r2, r, r);
    float qq = fmaf(r2, fmaf(r2, 2.4801587e-5f, -1.3888889e-3f), 4.1666668e-2f);
    float c  = fmaf(qq * r2, r2, fmaf(r2, -0.5f, 1.f));
    int   qm = q & 3;
    float sv = (qm & 1) ? c : s;
    float cv = (qm & 1) ? s : c;
    if (qm == 1 || qm == 2) cv = -cv;
    if (qm == 2 || qm == 3) sv = -sv;
    *sp = sv; *cp = cv;
}
__device__ __forceinline__ u32 bfbits32(float v) {
    u32 r; asm("{ .reg .b16 h; cvt.rn.bf16.f32 h, %1; mov.b32 %0, {h, 0}; }" : "=r"(r) : "f"(v));
    return r & 0xFFFFu;
}
__device__ __forceinline__ void mma4(float* c, const u32* a, u32 b0, u32 b1) {
    asm("mma.sync.aligned.m16n8k16.row.col.f32.bf16.bf16.f32 "
        "{%0,%1,%2,%3}, {%4,%5,%6,%7}, {%8,%9}, {%0,%1,%2,%3};"
        : "+f"(c[0]), "+f"(c[1]), "+f"(c[2]), "+f"(c[3])
        : "r"(a[0]), "r"(a[1]), "r"(a[2]), "r"(a[3]), "r"(b0), "r"(b1));
}
__device__ __forceinline__ void split2(float v0, float v1, u32& hi, u32& lo) {
    u32 u0 = __float_as_uint(v0), u1 = __float_as_uint(v1);
    hi = __byte_perm(u0, u1, 0x7632);
    float l0 = v0 - __uint_as_float(u0 & 0xFFFF0000u);
    float l1 = v1 - __uint_as_float(u1 & 0xFFFF0000u);
    asm("cvt.rn.bf16x2.f32 %0, %1, %2;" : "=r"(lo) : "f"(l1), "f"(l0));
}

// Slab (per CTA): u32[2][4096]. Within a buf: hi plane [0,2048), lo plane [2048,4096).
// record = (tile*8 + ks)*128 + lane*4 + reg.

// MODE: 0 normal, 1 = L2 (shape partials + A-write), 2 = last (texture partials)
// hp: MODE1 -> 4 floats [tile*2+row]; MODE2 -> 12 floats [tile*6 + c*2 + row]
template <int NKS, int MODE>
__device__ __forceinline__ void run_layer(const uint4* __restrict__ wfrag,
                                          const float* __restrict__ bias,
                                          const u32* rbuf, u32* wbuf,
                                          int lane, int q, int w, float* hp)
{
    float acc[2][4][4];   // [tile][nt][reg]
#pragma unroll
    for (int t = 0; t < 2; t++)
#pragma unroll
        for (int nt = 0; nt < 4; nt++)
            acc[t][nt][0] = acc[t][nt][1] = acc[t][nt][2] = acc[t][nt][3] = 0.f;

#pragma unroll
    for (int ks = 0; ks < NKS; ks++) {
        uint4 h0v = *(const uint4*)(rbuf + (0 * 8 + ks) * 128 + lane * 4);
        uint4 l0v = *(const uint4*)(rbuf + 2048 + (0 * 8 + ks) * 128 + lane * 4);
        uint4 h1v = *(const uint4*)(rbuf + (1 * 8 + ks) * 128 + lane * 4);
        uint4 l1v = *(const uint4*)(rbuf + 2048 + (1 * 8 + ks) * 128 + lane * 4);
        u32 ah0[4] = { h0v.x, h0v.y, h0v.z, h0v.w };
        u32 al0[4] = { l0v.x, l0v.y, l0v.z, l0v.w };
        u32 ah1[4] = { h1v.x, h1v.y, h1v.z, h1v.w };
        u32 al1[4] = { l1v.x, l1v.y, l1v.z, l1v.w };
        const uint4* p = wfrag + (ks * 16 + w * 4) * 32 + lane;
        uint4 f0 = __ldg(p);
        uint4 f1 = __ldg(p + 32);
        uint4 f2 = __ldg(p + 64);
        uint4 f3 = __ldg(p + 96);
#pragma unroll
        for (int nt = 0; nt < 4; nt++) {
            uint4 f = (nt == 0) ? f0 : (nt == 1) ? f1 : (nt == 2) ? f2 : f3;
            mma4(acc[0][nt], ah0, f.x, f.y);
            mma4(acc[1][nt], ah1, f.x, f.y);
            mma4(acc[0][nt], ah0, f.z, f.w);
            mma4(acc[1][nt], ah1, f.z, f.w);
            mma4(acc[0][nt], al0, f.x, f.y);
            mma4(acc[1][nt], al1, f.x, f.y);
        }
    }
#pragma unroll
    for (int t = 0; t < 2; t++) {
#pragma unroll
        for (int nt = 0; nt < 4; nt++) {
            int gnt = w * 4 + nt;
            float2 b = __ldg((const float2*)(bias + gnt * 8 + 2 * q));
            float v0 = lrelu_s2(acc[t][nt][0] + b.x), v1 = lrelu_s2(acc[t][nt][1] + b.y);
            float v2 = lrelu_s2(acc[t][nt][2] + b.x), v3 = lrelu_s2(acc[t][nt][3] + b.y);
            int ch = gnt * 8 + 2 * q;
            if (MODE == 1) {
                float2 wv = __ldg((const float2*)(g_swsh + ch));
                hp[t * 2 + 0] = fmaf(v0, wv.x, fmaf(v1, wv.y, hp[t * 2 + 0]));
                hp[t * 2 + 1] = fmaf(v2, wv.x, fmaf(v3, wv.y, hp[t * 2 + 1]));
            }
            if (MODE == 2) {
#pragma unroll
                for (int c = 0; c < 3; c++) {
                    float2 wv = __ldg((const float2*)(g_swt2 + c * 128 + ch));
                    hp[t * 6 + c * 2 + 0] = fmaf(v0, wv.x, fmaf(v1, wv.y, hp[t * 6 + c * 2 + 0]));
                    hp[t * 6 + c * 2 + 1] = fmaf(v2, wv.x, fmaf(v3, wv.y, hp[t * 6 + c * 2 + 1]));
                }
            } else {
                int ks2 = gnt >> 1, hf = gnt & 1;
                u32 h0, l0, h1, l1;
                split2(v0, v1, h0, l0);
                split2(v2, v3, h1, l1);
                *(uint2*)(wbuf + (t * 8 + ks2) * 128 + lane * 4 + hf * 2)        = make_uint2(h0, h1);
                *(uint2*)(wbuf + 2048 + (t * 8 + ks2) * 128 + lane * 4 + hf * 2) = make_uint2(l0, l1);
            }
        }
    }
}

__global__ void prep_kernel(
    const float* __restrict__ ws0, const float* __restrict__ bs0, const float* __restrict__ sc,
    const float* __restrict__ ws1, const float* __restrict__ ws2, const float* __restrict__ wsh,
    const float* __restrict__ wt0, const float* __restrict__ bt0, const float* __restrict__ tc,
    const float* __restrict__ wt1, const float* __restrict__ wt2, int B)
{
    const float s0 = 1.f / sqrtf(96.f), s1 = 1.f / sqrtf(128.f), st0 = 1.f / sqrtf(192.f);
    int nth = blockDim.x * gridDim.x;
    int tid0 = blockIdx.x * blockDim.x + threadIdx.x;

    for (int l = 0; l < 5; l++) {
        int KS; const float* src; float scl; int srcw;
        if      (l == 0) { KS = 2; src = ws0; scl = s0;  srcw = 96;  }
        else if (l == 1) { KS = 8; src = ws1; scl = s1;  srcw = 128; }
        else if (l == 2) { KS = 8; src = ws2; scl = s1;  srcw = 128; }
        else if (l == 3) { KS = 8; src = wt0; scl = st0; srcw = 192; }
        else             { KS = 8; src = wt1; scl = s1;  srcw = 128; }
        int tot = KS * 512;
        for (int idx = tid0; idx < tot; idx += nth) {
            int ks = idx >> 9, rem = idx & 511, nt = rem >> 5, lane = rem & 31;
            int q = lane & 3, gg = lane >> 2;
            int n = nt * 8 + gg;
            int ka = ks * 16 + 2 * q;
            float w[4];
            w[0] = src[n * srcw + ka] * scl;
            w[1] = src[n * srcw + ka + 1] * scl;
            w[2] = src[n * srcw + ka + 8] * scl;
            w[3] = src[n * srcw + ka + 9] * scl;
            u32 h[4], lo[4];
            for (int i = 0; i < 4; i++) {
                u32 ub = __float_as_uint(w[i]) & 0xFFFF0000u;
                h[i] = ub >> 16;
                lo[i] = bfbits32(w[i] - __uint_as_float(ub));
            }
            uint4 f;
            f.x = h[0] | (h[1] << 16);
            f.y = h[2] | (h[3] << 16);
            f.z = lo[0] | (lo[1] << 16);
            f.w = lo[2] | (lo[3] << 16);
            g_Bfrag[l][(ks * 16 + nt) * 32 + lane] = f;
        }
    }
    for (int i = tid0; i < 128; i += nth) g_swsh[i] = wsh[i] * s1;
    for (int i = tid0; i < 384; i += nth) g_swt2[i] = wt2[i] * s1;
    for (int idx = tid0; idx < B * 128 && idx < 8 * 128; idx += nth) {
        int b = idx >> 7, j = idx & 127;
        float a = 0.f, t = 0.f;
        for (int m = 0; m < 64; m++) {
            a += sc[b * 64 + m] * ws0[j * 96 + 32 + m];
            t += tc[b * 64 + m] * wt0[j * 192 + 128 + m];
        }
        g_b0 [b * 128 + j] = bs0[j] + a * s0;
        g_bt0[b * 128 + j] = bt0[j] + t * st0;
    }
}

__global__ __launch_bounds__(128, 5)
void decoder_kernel(const float* __restrict__ coords,
                    const float* __restrict__ bs1, const float* __restrict__ bs2,
                    const float* __restrict__ bsh, const float* __restrict__ bt1,
                    const float* __restrict__ bt2,
                    float* __restrict__ out, int HW, int BHW)
{
    __shared__ __align__(16) u32 sA[2][4096];   // double-buffered A slab (hi/lo planes)
    __shared__ float sHd[4][2][8][6];           // head partials [warp][tile][g][val]

    int tid = threadIdx.x;
    int lane = tid & 31, w = tid >> 5;
    int q = lane & 3, g = lane >> 2;
    int base = blockIdx.x * 32;
    int batch = base / HW;

    // ---- embedding: warp w fills (tile = w>>1, ks = w&1) of buf0
    {
        int tw = w >> 1, ks0 = w & 1;
        float2 crd0 = __ldg(&((const float2*)coords)[base + tw * 16 + g]);
        float2 crd1 = __ldg(&((const float2*)coords)[base + tw * 16 + g + 8]);
#pragma unroll
        for (int h = 0; h < 2; h++) {
            int s = 4 * ks0 + 2 * h + (q >> 1);
            float scl = 0.1f * (float)(1 << s);
#pragma unroll
            for (int row = 0; row < 2; row++) {
                float cx = (row ? crd1.x : crd0.x) * scl;
                float cy = (row ? crd1.y : crd0.y) * scl;
                float sx, cxv, sy, cyv;
                my_sincos(cx, &sx, &cxv);
                my_sincos(cy, &sy, &cyv);
                float v0 = (q & 1) ? cxv : sx;
                float v1 = (q & 1) ? cyv : sy;
                u32 hi, lo;
                split2(v0, v1, hi, lo);
                sA[0][(tw * 8 + ks0) * 128 + lane * 4 + 2 * h + row]        = hi;
                sA[0][2048 + (tw * 8 + ks0) * 128 + lane * 4 + 2 * h + row] = lo;
            }
        }
    }
    __syncthreads();

    float dummy[1];
    run_layer<2, 0>(g_Bfrag[0], g_b0 + batch * 128, sA[0], sA[1], lane, q, w, dummy);  // L0
    __syncthreads();
    run_layer<8, 0>(g_Bfrag[1], bs1, sA[1], sA[0], lane, q, w, dummy);                 // L1
    __syncthreads();

    // L2 + shape head partials (this warp's 32 channels, both tiles)
    float pS[4] = {0.f, 0.f, 0.f, 0.f};
    run_layer<8, 1>(g_Bfrag[2], bs2, sA[0], sA[1], lane, q, w, pS);
#pragma unroll
    for (int i = 0; i < 4; i++) {
        pS[i] += __shfl_xor_sync(0xffffffffu, pS[i], 1);
        pS[i] += __shfl_xor_sync(0xffffffffu, pS[i], 2);
    }
    if (q == 0) {
        sHd[w][0][g][0] = pS[0]; sHd[w][0][g][1] = pS[1];
        sHd[w][1][g][0] = pS[2]; sHd[w][1][g][1] = pS[3];
    }
    __syncthreads();   // also publishes L2's A-writes (sA[1]) for T0

    if (w < 2 && q == 0) {
        int px0 = base + w * 16 + g, px1 = px0 + 8;
        float bv = __ldg(bsh);
        float s0v = sHd[0][w][g][0] + sHd[1][w][g][0] + sHd[2][w][g][0] + sHd[3][w][g][0] + bv;
        float s1v = sHd[0][w][g][1] + sHd[1][w][g][1] + sHd[2][w][g][1] + sHd[3][w][g][1] + bv;
        float2 c0 = __ldg(&((const float2*)coords)[px0]);
        float2 c1 = __ldg(&((const float2*)coords)[px1]);
        float r0 = sqrtf(c0.x * c0.x + c0.y * c0.y);
        float r1 = sqrtf(c1.x * c1.x + c1.y * c1.y);
        out[px0] = s0v * (1.f - tanhf(fmaxf(r0 - 1.f, 0.f)));
        out[px1] = s1v * (1.f - tanhf(fmaxf(r1 - 1.f, 0.f)));
    }

    run_layer<8, 0>(g_Bfrag[3], g_bt0 + batch * 128, sA[1], sA[0], lane, q, w, dummy); // T0
    __syncthreads();

    // T1 + texture head partials
    float pT[12] = {0.f};
    run_layer<8, 2>(g_Bfrag[4], bt1, sA[0], sA[1], lane, q, w, pT);
#pragma unroll
    for (int i = 0; i < 12; i++) {
        pT[i] += __shfl_xor_sync(0xffffffffu, pT[i], 1);
        pT[i] += __shfl_xor_sync(0xffffffffu, pT[i], 2);
    }
    if (q == 0) {
#pragma unroll
        for (int t = 0; t < 2; t++)
#pragma unroll
            for (int i = 0; i < 6; i++) sHd[w][t][g][i] = pT[t * 6 + i];
    }
    __syncthreads();

    if (w < 2 && q == 0) {
        int px0 = base + w * 16 + g, px1 = px0 + 8;
        float* tp = out + BHW;
#pragma unroll
        for (int c = 0; c < 3; c++) {
            float bv = __ldg(bt2 + c);
            float t0v = sHd[0][w][g][2 * c]     + sHd[1][w][g][2 * c]     + sHd[2][w][g][2 * c]     + sHd[3][w][g][2 * c]     + bv;
            float t1v = sHd[0][w][g][2 * c + 1] + sHd[1][w][g][2 * c + 1] + sHd[2][w][g][2 * c + 1] + sHd[3][w][g][2 * c + 1] + bv;
            tp[3 * px0 + c] = t0v;
            tp[3 * px1 + c] = t1v;
        }
    }
}

extern "C" void kernel_launch(void* const* d_in, const int* in_sizes, int n_in,
                              void* d_out, int out_size)
{
    const float* coords = (const float*)d_in[0];
    const float* sc  = (const float*)d_in[1];
    const float* tc  = (const float*)d_in[2];
    const float* ws0 = (const float*)d_in[3];  const float* bs0 = (const float*)d_in[4];
    const float* ws1 = (const float*)d_in[5];  const float* bs1 = (const float*)d_in[6];
    const float* ws2 = (const float*)d_in[7];  const float* bs2 = (const float*)d_in[8];
    const float* wsh = (const float*)d_in[9];  const float* bsh = (const float*)d_in[10];
    const float* wt0 = (const float*)d_in[11]; const float* bt0 = (const float*)d_in[12];
    const float* wt1 = (const float*)d_in[13]; const float* bt1 = (const float*)d_in[14];
    const float* wt2 = (const float*)d_in[15]; const float* bt2 = (const float*)d_in[16];
    float* out = (float*)d_out;

    int B   = in_sizes[1] / 64;
    int BHW = in_sizes[0] / 2;
    int HW  = BHW / B;

    prep_kernel<<<64, 256>>>(ws0, bs0, sc, ws1, ws2, wsh, wt0, bt0, tc, wt1, wt2, B);
    decoder_kernel<<<BHW / 32, 128>>>(coords, bs1, bs2, bsh, bt1, bt2, out, HW, BHW);
}

// round 16
// speedup vs baseline: 1.4251x; 1.0067x over previous
#include <cuda_runtime.h>
#include <math.h>

// SpritesAndTexturesCoordinateDecoder — bf16 split mma.sync decoder, v11.
// = v10 quad scheme, occupancy pushed to 6 CTAs/SM (24 warps):
// __launch_bounds__(128,6) -> ptxas reg target 85 (mandatory ~90; expects
// small cold-temp spills only).

typedef unsigned int u32;

__device__ __align__(16) uint4 g_Bfrag[5][4096];   // [(ks*16+gnt)*32+lane] {hiB0,hiB1,loB0,loB1}
__device__ float g_b0[8 * 128], g_bt0[8 * 128];
__device__ float g_swsh[128], g_swt2[384];

__device__ __forceinline__ float lrelu_s2(float v) {
    return fmaf(0.84852813742385703f, v, 0.56568542494923801f * fabsf(v));
}
__device__ __forceinline__ void my_sincos(float x, float* sp, float* cp) {
    float k = rintf(x * 0.63661977236758134f);
    int   q = (int)k;
    float r = fmaf(k, -1.5707963705062866f, x);
    r       = fmaf(k,  4.3711390001862456e-8f, r);
    float r2 = r * r;
    float p  = fmaf(r2, fmaf(r2, -1.9841271e-4f, 8.3333310e-3f), -1.6666667e-1f);
    float s  = fmaf(p * r2, r, r);
    float qq = fmaf(r2, fmaf(r2, 2.4801587e-5f, -1.3888889e-3f), 4.1666668e-2f);
    float c  = fmaf(qq * r2, r2, fmaf(r2, -0.5f, 1.f));
    int   qm = q & 3;
    float sv = (qm & 1) ? c : s;
    float cv = (qm & 1) ? s : c;
    if (qm == 1 || qm == 2) cv = -cv;
    if (qm == 2 || qm == 3) sv = -sv;
    *sp = sv; *cp = cv;
}
__device__ __forceinline__ u32 bfbits32(float v) {
    u32 r; asm("{ .reg .b16 h; cvt.rn.bf16.f32 h, %1; mov.b32 %0, {h, 0}; }" : "=r"(r) : "f"(v));
    return r & 0xFFFFu;
}
__device__ __forceinline__ void mma4(float* c, const u32* a, u32 b0, u32 b1) {
    asm("mma.sync.aligned.m16n8k16.row.col.f32.bf16.bf16.f32 "
        "{%0,%1,%2,%3}, {%4,%5,%6,%7}, {%8,%9}, {%0,%1,%2,%3};"
        : "+f"(c[0]), "+f"(c[1]), "+f"(c[2]), "+f"(c[3])
        : "r"(a[0]), "r"(a[1]), "r"(a[2]), "r"(a[3]), "r"(b0), "r"(b1));
}
__device__ __forceinline__ void split2(float v0, float v1, u32& hi, u32& lo) {
    u32 u0 = __float_as_uint(v0), u1 = __float_as_uint(v1);
    hi = __byte_perm(u0, u1, 0x7632);
    float l0 = v0 - __uint_as_float(u0 & 0xFFFF0000u);
    float l1 = v1 - __uint_as_float(u1 & 0xFFFF0000u);
    asm("cvt.rn.bf16x2.f32 %0, %1, %2;" : "=r"(lo) : "f"(l1), "f"(l0));
}

// Slab (per CTA): u32[2][4096]. Within a buf: hi plane [0,2048), lo plane [2048,4096).
// record = (tile*8 + ks)*128 + lane*4 + reg.

// MODE: 0 normal, 1 = L2 (shape partials + A-write), 2 = last (texture partials)
template <int NKS, int MODE>
__device__ __forceinline__ void run_layer(const uint4* __restrict__ wfrag,
                                          const float* __restrict__ bias,
                                          const u32* rbuf, u32* wbuf,
                                          int lane, int q, int w, float* hp)
{
    float acc[2][4][4];   // [tile][nt][reg]
#pragma unroll
    for (int t = 0; t < 2; t++)
#pragma unroll
        for (int nt = 0; nt < 4; nt++)
            acc[t][nt][0] = acc[t][nt][1] = acc[t][nt][2] = acc[t][nt][3] = 0.f;

#pragma unroll
    for (int ks = 0; ks < NKS; ks++) {
        uint4 h0v = *(const uint4*)(rbuf + (0 * 8 + ks) * 128 + lane * 4);
        uint4 l0v = *(const uint4*)(rbuf + 2048 + (0 * 8 + ks) * 128 + lane * 4);
        uint4 h1v = *(const uint4*)(rbuf + (1 * 8 + ks) * 128 + lane * 4);
        uint4 l1v = *(const uint4*)(rbuf + 2048 + (1 * 8 + ks) * 128 + lane * 4);
        u32 ah0[4] = { h0v.x, h0v.y, h0v.z, h0v.w };
        u32 al0[4] = { l0v.x, l0v.y, l0v.z, l0v.w };
        u32 ah1[4] = { h1v.x, h1v.y, h1v.z, h1v.w };
        u32 al1[4] = { l1v.x, l1v.y, l1v.z, l1v.w };
        const uint4* p = wfrag + (ks * 16 + w * 4) * 32 + lane;
        uint4 f0 = __ldg(p);
        uint4 f1 = __ldg(p + 32);
        uint4 f2 = __ldg(p + 64);
        uint4 f3 = __ldg(p + 96);
#pragma unroll
        for (int nt = 0; nt < 4; nt++) {
            uint4 f = (nt == 0) ? f0 : (nt == 1) ? f1 : (nt == 2) ? f2 : f3;
            mma4(acc[0][nt], ah0, f.x, f.y);
            mma4(acc[1][nt], ah1, f.x, f.y);
            mma4(acc[0][nt], ah0, f.z, f.w);
            mma4(acc[1][nt], ah1, f.z, f.w);
            mma4(acc[0][nt], al0, f.x, f.y);
            mma4(acc[1][nt], al1, f.x, f.y);
        }
    }
#pragma unroll
    for (int t = 0; t < 2; t++) {
#pragma unroll
        for (int nt = 0; nt < 4; nt++) {
            int gnt = w * 4 + nt;
            float2 b = __ldg((const float2*)(bias + gnt * 8 + 2 * q));
            float v0 = lrelu_s2(acc[t][nt][0] + b.x), v1 = lrelu_s2(acc[t][nt][1] + b.y);
            float v2 = lrelu_s2(acc[t][nt][2] + b.x), v3 = lrelu_s2(acc[t][nt][3] + b.y);
            int ch = gnt * 8 + 2 * q;
            if (MODE == 1) {
                float2 wv = __ldg((const float2*)(g_swsh + ch));
                hp[t * 2 + 0] = fmaf(v0, wv.x, fmaf(v1, wv.y, hp[t * 2 + 0]));
                hp[t * 2 + 1] = fmaf(v2, wv.x, fmaf(v3, wv.y, hp[t * 2 + 1]));
            }
            if (MODE == 2) {
#pragma unroll
                for (int c = 0; c < 3; c++) {
                    float2 wv = __ldg((const float2*)(g_swt2 + c * 128 + ch));
                    hp[t * 6 + c * 2 + 0] = fmaf(v0, wv.x, fmaf(v1, wv.y, hp[t * 6 + c * 2 + 0]));
                    hp[t * 6 + c * 2 + 1] = fmaf(v2, wv.x, fmaf(v3, wv.y, hp[t * 6 + c * 2 + 1]));
                }
            } else {
                int ks2 = gnt >> 1, hf = gnt & 1;
                u32 h0, l0, h1, l1;
                split2(v0, v1, h0, l0);
                split2(v2, v3, h1, l1);
                *(uint2*)(wbuf + (t * 8 + ks2) * 128 + lane * 4 + hf * 2)        = make_uint2(h0, h1);
                *(uint2*)(wbuf + 2048 + (t * 8 + ks2) * 128 + lane * 4 + hf * 2) = make_uint2(l0, l1);
            }
        }
    }
}

__global__ void prep_kernel(
    const float* __restrict__ ws0, const float* __restrict__ bs0, const float* __restrict__ sc,
    const float* __restrict__ ws1, const float* __restrict__ ws2, const float* __restrict__ wsh,
    const float* __restrict__ wt0, const float* __restrict__ bt0, const float* __restrict__ tc,
    const float* __restrict__ wt1, const float* __restrict__ wt2, int B)
{
    const float s0 = 1.f / sqrtf(96.f), s1 = 1.f / sqrtf(128.f), st0 = 1.f / sqrtf(192.f);
    int nth = blockDim.x * gridDim.x;
    int tid0 = blockIdx.x * blockDim.x + threadIdx.x;

    for (int l = 0; l < 5; l++) {
        int KS; const float* src; float scl; int srcw;
        if      (l == 0) { KS = 2; src = ws0; scl = s0;  srcw = 96;  }
        else if (l == 1) { KS = 8; src = ws1; scl = s1;  srcw = 128; }
        else if (l == 2) { KS = 8; src = ws2; scl = s1;  srcw = 128; }
        else if (l == 3) { KS = 8; src = wt0; scl = st0; srcw = 192; }
        else             { KS = 8; src = wt1; scl = s1;  srcw = 128; }
        int tot = KS * 512;
        for (int idx = tid0; idx < tot; idx += nth) {
            int ks = idx >> 9, rem = idx & 511, nt = rem >> 5, lane = rem & 31;
            int q = lane & 3, gg = lane >> 2;
            int n = nt * 8 + gg;
            int ka = ks * 16 + 2 * q;
            float w[4];
            w[0] = src[n * srcw + ka] * scl;
            w[1] = src[n * srcw + ka + 1] * scl;
            w[2] = src[n * srcw + ka + 8] * scl;
            w[3] = src[n * srcw + ka + 9] * scl;
            u32 h[4], lo[4];
            for (int i = 0; i < 4; i++) {
                u32 ub = __float_as_uint(w[i]) & 0xFFFF0000u;
                h[i] = ub >> 16;
                lo[i] = bfbits32(w[i] - __uint_as_float(ub));
            }
            uint4 f;
            f.x = h[0] | (h[1] << 16);
            f.y = h[2] | (h[3] << 16);
            f.z = lo[0] | (lo[1] << 16);
            f.w = lo[2] | (lo[3] << 16);
            g_Bfrag[l][(ks * 16 + nt) * 32 + lane] = f;
        }
    }
    for (int i = tid0; i < 128; i += nth) g_swsh[i] = wsh[i] * s1;
    for (int i = tid0; i < 384; i += nth) g_swt2[i] = wt2[i] * s1;
    for (int idx = tid0; idx < B * 128 && idx < 8 * 128; idx += nth) {
        int b = idx >> 7, j = idx & 127;
        float a = 0.f, t = 0.f;
        for (int m = 0; m < 64; m++) {
            a += sc[b * 64 + m] * ws0[j * 96 + 32 + m];
            t += tc[b * 64 + m] * wt0[j * 192 + 128 + m];
        }
        g_b0 [b * 128 + j] = bs0[j] + a * s0;
        g_bt0[b * 128 + j] = bt0[j] + t * st0;
    }
}

__global__ __launch_bounds__(128, 6)
void decoder_kernel(const float* __restrict__ coords,
                    const float* __restrict__ bs1, const float* __restrict__ bs2,
                    const float* __restrict__ bsh, const float* __restrict__ bt1,
                    const float* __restrict__ bt2,
                    float* __restrict__ out, int HW, int BHW)
{
    __shared__ __align__(16) u32 sA[2][4096];   // double-buffered A slab (hi/lo planes)
    __shared__ float sHd[4][2][8][6];           // head partials [warp][tile][g][val]

    int tid = threadIdx.x;
    int lane = tid & 31, w = tid >> 5;
    int q = lane & 3, g = lane >> 2;
    int base = blockIdx.x * 32;
    int batch = base / HW;

    // ---- embedding: warp w fills (tile = w>>1, ks = w&1) of buf0
    {
        int tw = w >> 1, ks0 = w & 1;
        float2 crd0 = __ldg(&((const float2*)coords)[base + tw * 16 + g]);
        float2 crd1 = __ldg(&((const float2*)coords)[base + tw * 16 + g + 8]);
#pragma unroll
        for (int h = 0; h < 2; h++) {
            int s = 4 * ks0 + 2 * h + (q >> 1);
            float scl = 0.1f * (float)(1 << s);
#pragma unroll
            for (int row = 0; row < 2; row++) {
                float cx = (row ? crd1.x : crd0.x) * scl;
                float cy = (row ? crd1.y : crd0.y) * scl;
                float sx, cxv, sy, cyv;
                my_sincos(cx, &sx, &cxv);
                my_sincos(cy, &sy, &cyv);
                float v0 = (q & 1) ? cxv : sx;
                float v1 = (q & 1) ? cyv : sy;
                u32 hi, lo;
                split2(v0, v1, hi, lo);
                sA[0][(tw * 8 + ks0) * 128 + lane * 4 + 2 * h + row]        = hi;
                sA[0][2048 + (tw * 8 + ks0) * 128 + lane * 4 + 2 * h + row] = lo;
            }
        }
    }
    __syncthreads();

    float dummy[1];
    run_layer<2, 0>(g_Bfrag[0], g_b0 + batch * 128, sA[0], sA[1], lane, q, w, dummy);  // L0
    __syncthreads();
    run_layer<8, 0>(g_Bfrag[1], bs1, sA[1], sA[0], lane, q, w, dummy);                 // L1
    __syncthreads();

    // L2 + shape head partials (this warp's 32 channels, both tiles)
    float pS[4] = {0.f, 0.f, 0.f, 0.f};
    run_layer<8, 1>(g_Bfrag[2], bs2, sA[0], sA[1], lane, q, w, pS);
#pragma unroll
    for (int i = 0; i < 4; i++) {
        pS[i] += __shfl_xor_sync(0xffffffffu, pS[i], 1);
        pS[i] += __shfl_xor_sync(0xffffffffu, pS[i], 2);
    }
    if (q == 0) {
        sHd[w][0][g][0] = pS[0]; sHd[w][0][g][1] = pS[1];
        sHd[w][1][g][0] = pS[2]; sHd[w][1][g][1] = pS[3];
    }
    __syncthreads();   // also publishes L2's A-writes (sA[1]) for T0

    if (w < 2 && q == 0) {
        int px0 = base + w * 16 + g, px1 = px0 + 8;
        float bv = __ldg(bsh);
        float s0v = sHd[0][w][g][0] + sHd[1][w][g][0] + sHd[2][w][g][0] + sHd[3][w][g][0] + bv;
        float s1v = sHd[0][w][g][1] + sHd[1][w][g][1] + sHd[2][w][g][1] + sHd[3][w][g][1] + bv;
        float2 c0 = __ldg(&((const float2*)coords)[px0]);
        float2 c1 = __ldg(&((const float2*)coords)[px1]);
        float r0 = sqrtf(c0.x * c0.x + c0.y * c0.y);
        float r1 = sqrtf(c1.x * c1.x + c1.y * c1.y);
        out[px0] = s0v * (1.f - tanhf(fmaxf(r0 - 1.f, 0.f)));
        out[px1] = s1v * (1.f - tanhf(fmaxf(r1 - 1.f, 0.f)));
    }

    run_layer<8, 0>(g_Bfrag[3], g_bt0 + batch * 128, sA[1], sA[0], lane, q, w, dummy); // T0
    __syncthreads();

    // T1 + texture head partials
    float pT[12] = {0.f};
    run_layer<8, 2>(g_Bfrag[4], bt1, sA[0], sA[1], lane, q, w, pT);
#pragma unroll
    for (int i = 0; i < 12; i++) {
        pT[i] += __shfl_xor_sync(0xffffffffu, pT[i], 1);
        pT[i] += __shfl_xor_sync(0xffffffffu, pT[i], 2);
    }
    if (q == 0) {
#pragma unroll
        for (int t = 0; t < 2; t++)
#pragma unroll
            for (int i = 0; i < 6; i++) sHd[w][t][g][i] = pT[t * 6 + i];
    }
    __syncthreads();

    if (w < 2 && q == 0) {
        int px0 = base + w * 16 + g, px1 = px0 + 8;
        float* tp = out + BHW;
#pragma unroll
        for (int c = 0; c < 3; c++) {
            float bv = __ldg(bt2 + c);
            float t0v = sHd[0][w][g][2 * c]     + sHd[1][w][g][2 * c]     + sHd[2][w][g][2 * c]     + sHd[3][w][g][2 * c]     + bv;
            float t1v = sHd[0][w][g][2 * c + 1] + sHd[1][w][g][2 * c + 1] + sHd[2][w][g][2 * c + 1] + sHd[3][w][g][2 * c + 1] + bv;
            tp[3 * px0 + c] = t0v;
            tp[3 * px1 + c] = t1v;
        }
    }
}

extern "C" void kernel_launch(void* const* d_in, const int* in_sizes, int n_in,
                              void* d_out, int out_size)
{
    const float* coords = (const float*)d_in[0];
    const float* sc  = (const float*)d_in[1];
    const float* tc  = (const float*)d_in[2];
    const float* ws0 = (const float*)d_in[3];  const float* bs0 = (const float*)d_in[4];
    const float* ws1 = (const float*)d_in[5];  const float* bs1 = (const float*)d_in[6];
    const float* ws2 = (const float*)d_in[7];  const float* bs2 = (const float*)d_in[8];
    const float* wsh = (const float*)d_in[9];  const float* bsh = (const float*)d_in[10];
    const float* wt0 = (const float*)d_in[11]; const float* bt0 = (const float*)d_in[12];
    const float* wt1 = (const float*)d_in[13]; const float* bt1 = (const float*)d_in[14];
    const float* wt2 = (const float*)d_in[15]; const float* bt2 = (const float*)d_in[16];
    float* out = (float*)d_out;

    int B   = in_sizes[1] / 64;
    int BHW = in_sizes[0] / 2;
    int HW  = BHW / B;

    prep_kernel<<<64, 256>>>(ws0, bs0, sc, ws1, ws2, wsh, wt0, bt0, tc, wt1, wt2, B);
    decoder_kernel<<<BHW / 32, 128>>>(coords, bs1, bs2, bsh, bt1, bt2, out, HW, BHW);
}